// round 11
// baseline (speedup 1.0000x reference)
#include <cuda_runtime.h>
#include <cuda_fp16.h>
#include <math.h>
#include <stdint.h>

#define B_   4
#define LQ   1024
#define LK   2048
#define E_   768
#define H_   16
#define HD_  48
#define BH_  (B_*H_)

// ---------------- scratch (device globals) ----------------
__device__ __half g_qh[BH_*LQ*HD_];                // fp16 q  [b][h][lq][d]
__device__ __half g_kh[BH_*LK*HD_];                // fp16 k
__device__ __half g_vh[BH_*LK*HD_];                // fp16 v
__device__ __half g_wh[3*E_*E_];                   // fp16 in_proj_w
__device__ __half g_owh[E_*E_];                    // fp16 out_w
__device__ __half g_s[(size_t)BH_*LQ*LK];          // exp(scores) fp16, unnormalized (268MB)
__device__ float  g_linv[BH_*LQ];                  // 1/rowsum (fp32)
__device__ __half g_ctxh[B_*LQ*E_];                // context fp16
__device__ float  g_ao[B_*LQ*E_];                  // attn_output fp32
__device__ float  g_pin_part[B_*8*1536];
__device__ float  g_gate[B_*3];

// output layout: output | attn_weights | num_heads | scale_factor | gate_value
#define OUT_ATTN ((size_t)B_*LQ*E_)
#define OUT_NH   (OUT_ATTN + (size_t)B_*LQ*LK)
#define OUT_SF   (OUT_NH + 4)
#define OUT_GV   (OUT_SF + 4)

// ---------------- helpers ----------------
__device__ __forceinline__ float fast_exp2(float x) {
    x = fmaxf(x, -120.0f);
    float k = rintf(x);
    float f = x - k;
    float p = 1.33336498e-3f;
    p = fmaf(p, f, 9.61011940e-3f);
    p = fmaf(p, f, 5.55041086e-2f);
    p = fmaf(p, f, 2.40226507e-1f);
    p = fmaf(p, f, 6.93147182e-1f);
    p = fmaf(p, f, 1.0f);
    int ik = (int)k;
    return p * __int_as_float((ik + 127) << 23);
}

__device__ __forceinline__ uint32_t smem_u32(const void* p) {
    uint32_t a;
    asm("{ .reg .u64 t; cvta.to.shared.u64 t, %1; cvt.u32.u64 %0, t; }" : "=r"(a) : "l"(p));
    return a;
}

__device__ __forceinline__ void ldsm_x4(uint32_t& r0, uint32_t& r1, uint32_t& r2, uint32_t& r3, uint32_t addr) {
    asm volatile("ldmatrix.sync.aligned.m8n8.x4.shared.b16 {%0,%1,%2,%3}, [%4];"
                 : "=r"(r0), "=r"(r1), "=r"(r2), "=r"(r3) : "r"(addr));
}
__device__ __forceinline__ void ldsm_x4_t(uint32_t& r0, uint32_t& r1, uint32_t& r2, uint32_t& r3, uint32_t addr) {
    asm volatile("ldmatrix.sync.aligned.m8n8.x4.trans.shared.b16 {%0,%1,%2,%3}, [%4];"
                 : "=r"(r0), "=r"(r1), "=r"(r2), "=r"(r3) : "r"(addr));
}
__device__ __forceinline__ void ldsm_x2(uint32_t& r0, uint32_t& r1, uint32_t addr) {
    asm volatile("ldmatrix.sync.aligned.m8n8.x2.shared.b16 {%0,%1}, [%2];"
                 : "=r"(r0), "=r"(r1) : "r"(addr));
}
__device__ __forceinline__ void mma16816(float c[4], const uint32_t a[4], uint32_t b0, uint32_t b1) {
    asm volatile("mma.sync.aligned.m16n8k16.row.col.f32.f16.f16.f32 "
                 "{%0,%1,%2,%3}, {%4,%5,%6,%7}, {%8,%9}, {%0,%1,%2,%3};"
                 : "+f"(c[0]), "+f"(c[1]), "+f"(c[2]), "+f"(c[3])
                 : "r"(a[0]), "r"(a[1]), "r"(a[2]), "r"(a[3]), "r"(b0), "r"(b1));
}
__device__ __forceinline__ void cp_async16(uint32_t dst, const void* src) {
    asm volatile("cp.async.cg.shared.global [%0], [%1], 16;" :: "r"(dst), "l"(src));
}
__device__ __forceinline__ void cp_commit() { asm volatile("cp.async.commit_group;"); }
__device__ __forceinline__ void cp_wait0()  { asm volatile("cp.async.wait_group 0;" ::: "memory"); }
__device__ __forceinline__ void stcs32(void* p, uint32_t v) {
    asm volatile("st.global.cs.b32 [%0], %1;" :: "l"(p), "r"(v));
}

__device__ __forceinline__ float block_reduce_sum(float v, float* red) {
    int tid = threadIdx.x;
    #pragma unroll
    for (int o = 16; o > 0; o >>= 1) v += __shfl_xor_sync(0xffffffffu, v, o);
    if ((tid & 31) == 0) red[tid >> 5] = v;
    __syncthreads();
    if (tid == 0) {
        float s = red[0];
        for (int i = 1; i < (int)(blockDim.x >> 5); i++) s += red[i];
        red[0] = s;
    }
    __syncthreads();
    float r = red[0];
    __syncthreads();
    return r;
}

// ---------------- 0) convert weights to fp16 ----------------
__global__ void k_cvt_w(const float* __restrict__ ipw, const float* __restrict__ ow) {
    int idx = blockIdx.x * 256 + threadIdx.x;
    const int n1 = 3 * E_ * E_ / 4;
    const int n2 = E_ * E_ / 4;
    if (idx < n1) {
        float4 v = ((const float4*)ipw)[idx];
        __half2 h0 = __floats2half2_rn(v.x, v.y);
        __half2 h1 = __floats2half2_rn(v.z, v.w);
        ((uint2*)g_wh)[idx] = make_uint2(*(uint32_t*)&h0, *(uint32_t*)&h1);
    } else if (idx < n1 + n2) {
        int j = idx - n1;
        float4 v = ((const float4*)ow)[j];
        __half2 h0 = __floats2half2_rn(v.x, v.y);
        __half2 h1 = __floats2half2_rn(v.z, v.w);
        ((uint2*)g_owh)[j] = make_uint2(*(uint32_t*)&h0, *(uint32_t*)&h1);
    }
}

// ---------------- 1) column means (partials) ----------------
__global__ void k_colmean(const float* __restrict__ q, const float* __restrict__ k) {
    int ch = blockIdx.x, b = blockIdx.y, which = blockIdx.z;
    const float* src = which ? k : q;
    int L = which ? LK : LQ;
    int rows = L / 8;
    const float* base = src + ((size_t)b * L + (size_t)ch * rows) * E_;
    for (int c = threadIdx.x; c < E_; c += 256) {
        float s = 0.f;
        for (int r = 0; r < rows; r++) s += base[(size_t)r * E_ + c];
        g_pin_part[(b * 8 + ch) * 1536 + which * E_ + c] = s;
    }
}

// ---------------- 2) gate MLP ----------------
__global__ void k_mlp(const float* __restrict__ Wp1, const float* __restrict__ bp1,
                      const float* __restrict__ Wp2, const float* __restrict__ bp2,
                      const float* __restrict__ Wp3, const float* __restrict__ bp3,
                      float* __restrict__ out) {
    __shared__ float pin[1536];
    __shared__ float h1[768];
    __shared__ float h2[384];
    int b = blockIdx.x, tid = threadIdx.x;
    for (int c = tid; c < 1536; c += 256) {
        float s = 0.f;
        for (int ch = 0; ch < 8; ch++) s += g_pin_part[(b * 8 + ch) * 1536 + c];
        pin[c] = s * ((c < 768) ? (1.0f / LQ) : (1.0f / LK));
    }
    __syncthreads();
    for (int o = tid; o < 768; o += 256) {
        const float* w = Wp1 + (size_t)o * 1536;
        float s = bp1[o];
        for (int i = 0; i < 1536; i++) s = fmaf(pin[i], w[i], s);
        h1[o] = fmaxf(s, 0.f);
    }
    __syncthreads();
    for (int o = tid; o < 384; o += 256) {
        const float* w = Wp2 + (size_t)o * 768;
        float s = bp2[o];
        for (int i = 0; i < 768; i++) s = fmaf(h1[i], w[i], s);
        h2[o] = fmaxf(s, 0.f);
    }
    __syncthreads();
    if (tid < 3) {
        const float* w = Wp3 + tid * 384;
        float s = bp3[tid];
        for (int i = 0; i < 384; i++) s = fmaf(h2[i], w[i], s);
        float sig = 1.f / (1.f + __expf(-s));
        if (tid == 0) {
            float nh = rintf(sig * 15.f + 1.f);
            g_gate[b * 3 + 0] = nh;
            out[OUT_NH + b] = nh;
        } else if (tid == 1) {
            float sf = sig * 0.5f + 0.5f;
            g_gate[b * 3 + 1] = sf;
            out[OUT_SF + b] = sf;
        } else {
            g_gate[b * 3 + 2] = sig;
            out[OUT_GV + b] = sig;
        }
    }
}

// ---------------- 3) QKV projection via HMMA ----------------
#define QKLD 40
__global__ void __launch_bounds__(256) k_qkv_hmma(
    const float* __restrict__ query, const float* __restrict__ key,
    const float* __restrict__ value, const float* __restrict__ bias) {
    __shared__ __half sA[2][128 * QKLD];
    __shared__ __half sB[2][128 * QKLD];
    int yt = blockIdx.y;
    int z, tokbase, Lseq;
    const float* src;
    __half* dst;
    if (yt < 32)      { z = 0; src = query; tokbase = yt * 128;        Lseq = LQ; dst = g_qh; }
    else if (yt < 96) { z = 1; src = key;   tokbase = (yt - 32) * 128; Lseq = LK; dst = g_kh; }
    else              { z = 2; src = value; tokbase = (yt - 96) * 128; Lseq = LK; dst = g_vh; }
    int n0 = blockIdx.x * 128;
    const __half* Bw = g_wh + ((size_t)(z * E_ + n0)) * E_;
    int tid = threadIdx.x, lane = tid & 31, warp = tid >> 5;
    int wm = warp >> 1, wn = warp & 1;
    int ar[4], ac4[4];
    #pragma unroll
    for (int i = 0; i < 4; i++) { int f4 = tid + i * 256; ar[i] = f4 >> 3; ac4[i] = f4 & 7; }
    int br[2], bc8[2];
    #pragma unroll
    for (int i = 0; i < 2; i++) { int u4 = tid + i * 256; br[i] = u4 >> 2; bc8[i] = u4 & 3; }
    #pragma unroll
    for (int i = 0; i < 4; i++) {
        float4 v = *(const float4*)(src + (size_t)(tokbase + ar[i]) * E_ + ac4[i] * 4);
        __half2 h0 = __floats2half2_rn(v.x, v.y);
        __half2 h1 = __floats2half2_rn(v.z, v.w);
        *(uint2*)(sA[0] + ar[i] * QKLD + ac4[i] * 4) = make_uint2(*(uint32_t*)&h0, *(uint32_t*)&h1);
    }
    #pragma unroll
    for (int i = 0; i < 2; i++)
        *(uint4*)(sB[0] + br[i] * QKLD + bc8[i] * 8) = *(const uint4*)(Bw + (size_t)br[i] * E_ + bc8[i] * 8);
    __syncthreads();
    float acc[2][8][4];
    #pragma unroll
    for (int mf = 0; mf < 2; mf++)
        #pragma unroll
        for (int nf = 0; nf < 8; nf++)
            #pragma unroll
            for (int q = 0; q < 4; q++) acc[mf][nf][q] = 0.f;
    int buf = 0;
    float4 apf[4];
    uint4 bpf[2];
    for (int kc = 0; kc < 24; kc++) {
        bool more = (kc + 1) < 24;
        if (more) {
            int kb = (kc + 1) * 32;
            #pragma unroll
            for (int i = 0; i < 4; i++)
                apf[i] = *(const float4*)(src + (size_t)(tokbase + ar[i]) * E_ + kb + ac4[i] * 4);
            #pragma unroll
            for (int i = 0; i < 2; i++)
                bpf[i] = *(const uint4*)(Bw + (size_t)br[i] * E_ + kb + bc8[i] * 8);
        }
        #pragma unroll
        for (int ks = 0; ks < 2; ks++) {
            uint32_t a[2][4];
            #pragma unroll
            for (int mf = 0; mf < 2; mf++) {
                uint32_t addr = smem_u32(sA[buf] + (wm * 32 + mf * 16 + (lane & 15)) * QKLD + ks * 16 + (lane >> 4) * 8);
                ldsm_x4(a[mf][0], a[mf][1], a[mf][2], a[mf][3], addr);
            }
            #pragma unroll
            for (int nf = 0; nf < 8; nf++) {
                uint32_t b0, b1;
                uint32_t addr = smem_u32(sB[buf] + (wn * 64 + nf * 8 + (lane & 7)) * QKLD + ks * 16 + ((lane >> 3) & 1) * 8);
                ldsm_x2(b0, b1, addr);
                mma16816(acc[0][nf], a[0], b0, b1);
                mma16816(acc[1][nf], a[1], b0, b1);
            }
        }
        if (more) {
            int nb = buf ^ 1;
            #pragma unroll
            for (int i = 0; i < 4; i++) {
                __half2 h0 = __floats2half2_rn(apf[i].x, apf[i].y);
                __half2 h1 = __floats2half2_rn(apf[i].z, apf[i].w);
                *(uint2*)(sA[nb] + ar[i] * QKLD + ac4[i] * 4) = make_uint2(*(uint32_t*)&h0, *(uint32_t*)&h1);
            }
            #pragma unroll
            for (int i = 0; i < 2; i++)
                *(uint4*)(sB[nb] + br[i] * QKLD + bc8[i] * 8) = bpf[i];
            __syncthreads();
            buf = nb;
        }
    }
    int bb = tokbase / Lseq;
    int sbase = tokbase % Lseq;
    #pragma unroll
    for (int mf = 0; mf < 2; mf++) {
        int r0 = wm * 32 + mf * 16 + (lane >> 2);
        #pragma unroll
        for (int nf = 0; nf < 8; nf++) {
            int c0 = n0 + wn * 64 + nf * 8 + 2 * (lane & 3);
            int h = c0 / HD_, d = c0 % HD_;
            float bv0 = bias[z * E_ + c0], bv1 = bias[z * E_ + c0 + 1];
            size_t a0 = (((size_t)(bb * H_ + h)) * Lseq + sbase + r0) * HD_ + d;
            size_t a1 = (((size_t)(bb * H_ + h)) * Lseq + sbase + r0 + 8) * HD_ + d;
            *(__half2*)(dst + a0) = __floats2half2_rn(acc[mf][nf][0] + bv0, acc[mf][nf][1] + bv1);
            *(__half2*)(dst + a1) = __floats2half2_rn(acc[mf][nf][2] + bv0, acc[mf][nf][3] + bv1);
        }
    }
}

// ------- 4) FUSED scores+PV, 2 CTAs/SM: cp.async K/V pipeline, 64-col halves -------
#define SQLD 56
#define VLD  56
static constexpr int SMEM_FUSED =
    (128 * SQLD + 2 * 128 * SQLD + 2 * 128 * VLD) * 2 + LK * 4;   // 79872 B
__global__ void __launch_bounds__(256, 2) k_scores_pv(const unsigned char* __restrict__ mask) {
    extern __shared__ __align__(16) char smem_raw[];
    __half* sQ = (__half*)smem_raw;                        // 128*SQLD
    __half* sK = sQ + 128 * SQLD;                          // 2 x 128*SQLD
    __half* sV = sK + 2 * 128 * SQLD;                      // 2 x 128*VLD
    float*  sMsk = (float*)(sV + 2 * 128 * VLD);           // LK
    int bh = blockIdx.y, m0 = blockIdx.x * 128, b = bh >> 4;
    int tid = threadIdx.x, lane = tid & 31, w = tid >> 5;
    const __half* Qsrc = g_qh + ((size_t)bh * LQ + m0) * HD_;
    const __half* Ksrc = g_kh + (size_t)bh * LK * HD_;
    const __half* Vsrc = g_vh + (size_t)bh * LK * HD_;
    // stage Q (768 uint4) + mask
    #pragma unroll
    for (int i = 0; i < 3; i++) {
        int idx = tid + i * 256;
        int r = idx / 6, c8 = idx % 6;
        *(uint4*)(sQ + r * SQLD + c8 * 8) = *(const uint4*)(Qsrc + (size_t)r * HD_ + c8 * 8);
    }
    #pragma unroll
    for (int i = 0; i < 8; i++) {
        int c = tid + i * 256;
        sMsk[c] = mask[b * LK + c] ? 0.f : 1.f;
    }
    // cp.async K,V tile 0
    int rr[3], cc[3];
    #pragma unroll
    for (int i = 0; i < 3; i++) { int idx = tid + i * 256; rr[i] = idx / 6; cc[i] = idx % 6; }
    #pragma unroll
    for (int i = 0; i < 3; i++) {
        cp_async16(smem_u32(sK + rr[i] * SQLD + cc[i] * 8), Ksrc + (size_t)rr[i] * HD_ + cc[i] * 8);
        cp_async16(smem_u32(sV + rr[i] * VLD + cc[i] * 8),  Vsrc + (size_t)rr[i] * HD_ + cc[i] * 8);
    }
    cp_commit();
    cp_wait0();
    __syncthreads();
    // Q fragments: warp rows w*16..+16, 3 k16 steps
    uint32_t aQ[3][4];
    #pragma unroll
    for (int ks = 0; ks < 3; ks++) {
        uint32_t addr = smem_u32(sQ + (w * 16 + (lane & 15)) * SQLD + ks * 16 + (lane >> 4) * 8);
        ldsm_x4(aQ[ks][0], aQ[ks][1], aQ[ks][2], aQ[ks][3], addr);
    }
    float rsum[2] = {0.f, 0.f};
    float acc_o[6][4];
    #pragma unroll
    for (int nfv = 0; nfv < 6; nfv++)
        #pragma unroll
        for (int q = 0; q < 4; q++) acc_o[nfv][q] = 0.f;
    __half* srow = g_s + (size_t)bh * LQ * LK;
    const float cs = 0.14433757f * 1.44269504f;
    int lr0 = w * 16 + (lane >> 2);
    int buf = 0;
    for (int t = 0; t < 16; t++) {
        bool more = (t + 1) < 16;
        if (more) {
            const __half* Kn = Ksrc + (size_t)(t + 1) * 128 * HD_;
            const __half* Vn = Vsrc + (size_t)(t + 1) * 128 * HD_;
            int nb = buf ^ 1;
            #pragma unroll
            for (int i = 0; i < 3; i++) {
                cp_async16(smem_u32(sK + nb * 128 * SQLD + rr[i] * SQLD + cc[i] * 8),
                           Kn + (size_t)rr[i] * HD_ + cc[i] * 8);
                cp_async16(smem_u32(sV + nb * 128 * VLD + rr[i] * VLD + cc[i] * 8),
                           Vn + (size_t)rr[i] * HD_ + cc[i] * 8);
            }
            cp_commit();
        }
        #pragma unroll
        for (int hf = 0; hf < 2; hf++) {
            // QK: this warp's 16 rows x 64 cols
            float acc[8][4];
            #pragma unroll
            for (int nf = 0; nf < 8; nf++)
                #pragma unroll
                for (int q = 0; q < 4; q++) acc[nf][q] = 0.f;
            #pragma unroll
            for (int ks = 0; ks < 3; ks++) {
                #pragma unroll
                for (int nfp = 0; nfp < 4; nfp++) {
                    uint32_t m0r, m1r, m2r, m3r;
                    uint32_t addr = smem_u32(sK + buf * 128 * SQLD +
                                             (hf * 64 + nfp * 16 + (lane & 15)) * SQLD + ks * 16 + (lane >> 4) * 8);
                    ldsm_x4(m0r, m1r, m2r, m3r, addr);
                    mma16816(acc[2 * nfp],     aQ[ks], m0r, m2r);
                    mma16816(acc[2 * nfp + 1], aQ[ks], m1r, m3r);
                }
            }
            // epilogue: exp, mask, rowsum, store fp16 (.cs), pack A-frags
            int n0 = t * 128 + hf * 64;
            uint32_t ph01[8], ph23[8];
            #pragma unroll
            for (int nf = 0; nf < 8; nf++) {
                int c = n0 + nf * 8 + 2 * (lane & 3);
                float mk0 = sMsk[c], mk1 = sMsk[c + 1];
                float p00 = fast_exp2(acc[nf][0] * cs) * mk0;
                float p01 = fast_exp2(acc[nf][1] * cs) * mk1;
                float p10 = fast_exp2(acc[nf][2] * cs) * mk0;
                float p11 = fast_exp2(acc[nf][3] * cs) * mk1;
                rsum[0] += p00 + p01;
                rsum[1] += p10 + p11;
                __half2 h0 = __floats2half2_rn(p00, p01);
                __half2 h1 = __floats2half2_rn(p10, p11);
                ph01[nf] = *(uint32_t*)&h0;
                ph23[nf] = *(uint32_t*)&h1;
                stcs32(srow + (size_t)(m0 + lr0) * LK + c,     ph01[nf]);
                stcs32(srow + (size_t)(m0 + lr0 + 8) * LK + c, ph23[nf]);
            }
            // PV: ctx += P_half(16x64) @ V_half(64x48)
            #pragma unroll
            for (int ksl = 0; ksl < 4; ksl++) {
                uint32_t pA[4] = {ph01[2 * ksl], ph23[2 * ksl], ph01[2 * ksl + 1], ph23[2 * ksl + 1]};
                #pragma unroll
                for (int nfvp = 0; nfvp < 3; nfvp++) {
                    uint32_t v0, v1, v2, v3;
                    uint32_t addr = smem_u32(sV + buf * 128 * VLD +
                                             (hf * 64 + ksl * 16 + (lane & 15)) * VLD + nfvp * 16 + (lane >> 4) * 8);
                    ldsm_x4_t(v0, v1, v2, v3, addr);
                    mma16816(acc_o[2 * nfvp],     pA, v0, v1);
                    mma16816(acc_o[2 * nfvp + 1], pA, v2, v3);
                }
            }
        }
        if (more) {
            cp_wait0();
            __syncthreads();
            buf ^= 1;
        }
    }
    // row sums: reduce over quad lanes (cols)
    #pragma unroll
    for (int r = 0; r < 2; r++) {
        rsum[r] += __shfl_xor_sync(0xffffffffu, rsum[r], 1);
        rsum[r] += __shfl_xor_sync(0xffffffffu, rsum[r], 2);
    }
    float linv0 = 1.0f / rsum[0];
    float linv1 = 1.0f / rsum[1];
    if ((lane & 3) == 0) {
        g_linv[bh * LQ + m0 + lr0]     = linv0;
        g_linv[bh * LQ + m0 + lr0 + 8] = linv1;
    }
    // write ctx (fp16, per-token layout)
    int h = bh & 15;
    #pragma unroll
    for (int nfv = 0; nfv < 6; nfv++) {
        int d = nfv * 8 + 2 * (lane & 3);
        __half* dst0 = g_ctxh + ((size_t)b * LQ + m0 + lr0) * E_ + h * HD_ + d;
        __half* dst1 = g_ctxh + ((size_t)b * LQ + m0 + lr0 + 8) * E_ + h * HD_ + d;
        *(__half2*)dst0 = __floats2half2_rn(acc_o[nfv][0] * linv0, acc_o[nfv][1] * linv0);
        *(__half2*)dst1 = __floats2half2_rn(acc_o[nfv][2] * linv1, acc_o[nfv][3] * linv1);
    }
}

// ---------------- 6) attn_weights = mean over heads (normalized), fp16 streaming reads ----------------
__global__ void __launch_bounds__(256) k_meanheads(float* __restrict__ out) {
    size_t idx8 = (size_t)blockIdx.x * 256 + threadIdx.x;
    const size_t per_b8 = (size_t)LQ * LK / 8;
    int b = (int)(idx8 / per_b8);
    size_t rem8 = idx8 % per_b8;
    int q = (int)(rem8 >> 8);
    const uint4* base = (const uint4*)g_s + (size_t)b * H_ * per_b8 + rem8;
    float acc[8];
    #pragma unroll
    for (int j = 0; j < 8; j++) acc[j] = 0.f;
    #pragma unroll
    for (int h = 0; h < H_; h++) {
        float inv = g_linv[(b * H_ + h) * LQ + q];
        uint4 v = __ldcs(base + (size_t)h * per_b8);
        __half2* hh = (__half2*)&v;
        #pragma unroll
        for (int j = 0; j < 4; j++) {
            float2 f = __half22float2(hh[j]);
            acc[2 * j + 0] = fmaf(f.x, inv, acc[2 * j + 0]);
            acc[2 * j + 1] = fmaf(f.y, inv, acc[2 * j + 1]);
        }
    }
    const float ih = 1.0f / H_;
    float* dst = out + OUT_ATTN + idx8 * 8;
    *(float4*)(dst)     = make_float4(acc[0] * ih, acc[1] * ih, acc[2] * ih, acc[3] * ih);
    *(float4*)(dst + 4) = make_float4(acc[4] * ih, acc[5] * ih, acc[6] * ih, acc[7] * ih);
}

// ---------------- 8) attn_output = ctx @ out_w^T + out_b via HMMA ----------------
__global__ void __launch_bounds__(256) k_outproj_hmma(const float* __restrict__ out_b) {
    __shared__ __half sA[2][128 * QKLD];
    __shared__ __half sB[2][128 * QKLD];
    int m0 = blockIdx.y * 128, n0 = blockIdx.x * 128;
    int tid = threadIdx.x, lane = tid & 31, warp = tid >> 5;
    int wm = warp >> 1, wn = warp & 1;
    const __half* Asrc = g_ctxh + (size_t)m0 * E_;
    const __half* Bw = g_owh + (size_t)n0 * E_;
    int ur[2], uc8[2];
    #pragma unroll
    for (int i = 0; i < 2; i++) { int u4 = tid + i * 256; ur[i] = u4 >> 2; uc8[i] = u4 & 3; }
    #pragma unroll
    for (int i = 0; i < 2; i++) {
        *(uint4*)(sA[0] + ur[i] * QKLD + uc8[i] * 8) = *(const uint4*)(Asrc + (size_t)ur[i] * E_ + uc8[i] * 8);
        *(uint4*)(sB[0] + ur[i] * QKLD + uc8[i] * 8) = *(const uint4*)(Bw + (size_t)ur[i] * E_ + uc8[i] * 8);
    }
    __syncthreads();
    float acc[2][8][4];
    #pragma unroll
    for (int mf = 0; mf < 2; mf++)
        #pragma unroll
        for (int nf = 0; nf < 8; nf++)
            #pragma unroll
            for (int q = 0; q < 4; q++) acc[mf][nf][q] = 0.f;
    int buf = 0;
    uint4 apf[2], bpf[2];
    for (int kc = 0; kc < 24; kc++) {
        bool more = (kc + 1) < 24;
        if (more) {
            int kb = (kc + 1) * 32;
            #pragma unroll
            for (int i = 0; i < 2; i++) {
                apf[i] = *(const uint4*)(Asrc + (size_t)ur[i] * E_ + kb + uc8[i] * 8);
                bpf[i] = *(const uint4*)(Bw + (size_t)ur[i] * E_ + kb + uc8[i] * 8);
            }
        }
        #pragma unroll
        for (int ks = 0; ks < 2; ks++) {
            uint32_t a[2][4];
            #pragma unroll
            for (int mf = 0; mf < 2; mf++) {
                uint32_t addr = smem_u32(sA[buf] + (wm * 32 + mf * 16 + (lane & 15)) * QKLD + ks * 16 + (lane >> 4) * 8);
                ldsm_x4(a[mf][0], a[mf][1], a[mf][2], a[mf][3], addr);
            }
            #pragma unroll
            for (int nf = 0; nf < 8; nf++) {
                uint32_t b0, b1;
                uint32_t addr = smem_u32(sB[buf] + (wn * 64 + nf * 8 + (lane & 7)) * QKLD + ks * 16 + ((lane >> 3) & 1) * 8);
                ldsm_x2(b0, b1, addr);
                mma16816(acc[0][nf], a[0], b0, b1);
                mma16816(acc[1][nf], a[1], b0, b1);
            }
        }
        if (more) {
            int nb = buf ^ 1;
            #pragma unroll
            for (int i = 0; i < 2; i++) {
                *(uint4*)(sA[nb] + ur[i] * QKLD + uc8[i] * 8) = apf[i];
                *(uint4*)(sB[nb] + ur[i] * QKLD + uc8[i] * 8) = bpf[i];
            }
            __syncthreads();
            buf = nb;
        }
    }
    #pragma unroll
    for (int mf = 0; mf < 2; mf++) {
        int r0 = m0 + wm * 32 + mf * 16 + (lane >> 2);
        #pragma unroll
        for (int nf = 0; nf < 8; nf++) {
            int c0 = n0 + wn * 64 + nf * 8 + 2 * (lane & 3);
            float bv0 = out_b[c0], bv1 = out_b[c0 + 1];
            *(float2*)(g_ao + (size_t)r0 * E_ + c0)       = make_float2(acc[mf][nf][0] + bv0, acc[mf][nf][1] + bv1);
            *(float2*)(g_ao + (size_t)(r0 + 8) * E_ + c0) = make_float2(acc[mf][nf][2] + bv0, acc[mf][nf][3] + bv1);
        }
    }
}

// ---------------- 9) gate + residual + layernorm ----------------
__global__ void __launch_bounds__(256) k_final(const float* __restrict__ query,
                                               const float* __restrict__ ln_g,
                                               const float* __restrict__ ln_b,
                                               float* __restrict__ out) {
    __shared__ float xs[768];
    __shared__ float red[8];
    int t = blockIdx.x;
    int b = t >> 10;
    float sf = g_gate[b * 3 + 1], gv = g_gate[b * 3 + 2];
    const float* qrow = query + (size_t)t * E_;
    const float* arow = g_ao + (size_t)t * E_;
    int tid = threadIdx.x;
    float lsum = 0.f;
    for (int c = tid; c < E_; c += 256) {
        float q = qrow[c], a = arow[c];
        float gated = q * (1.f - gv) + a * sf * gv;
        float x = q + gated;
        xs[c] = x;
        lsum += x;
    }
    float mu = block_reduce_sum(lsum, red) * (1.0f / E_);
    float lv = 0.f;
    for (int c = tid; c < E_; c += 256) {
        float d = xs[c] - mu;
        lv += d * d;
    }
    float var = block_reduce_sum(lv, red) * (1.0f / E_);
    float inv = rsqrtf(var + 1e-5f);
    for (int c = tid; c < E_; c += 256)
        out[(size_t)t * E_ + c] = (xs[c] - mu) * inv * ln_g[c] + ln_b[c];
}

// ---------------- launcher (multi-stream fork/join, capture-safe) ----------------
extern "C" void kernel_launch(void* const* d_in, const int* in_sizes, int n_in,
                              void* d_out, int out_size) {
    const float* query = (const float*)d_in[0];
    const float* key   = (const float*)d_in[1];
    const float* value = (const float*)d_in[2];
    const unsigned char* mask = (const unsigned char*)d_in[3];
    const float* Wp1 = (const float*)d_in[4];
    const float* bp1 = (const float*)d_in[5];
    const float* Wp2 = (const float*)d_in[6];
    const float* bp2 = (const float*)d_in[7];
    const float* Wp3 = (const float*)d_in[8];
    const float* bp3 = (const float*)d_in[9];
    const float* in_proj_w = (const float*)d_in[10];
    const float* in_proj_b = (const float*)d_in[11];
    const float* out_w = (const float*)d_in[12];
    const float* out_b = (const float*)d_in[13];
    const float* ln_g  = (const float*)d_in[14];
    const float* ln_b  = (const float*)d_in[15];
    float* out = (float*)d_out;

    static bool once = []() {
        cudaFuncSetAttribute(k_scores_pv, cudaFuncAttributeMaxDynamicSharedMemorySize, SMEM_FUSED);
        return true;
    }();
    (void)once;

    static cudaStream_t s1 = []() {
        cudaStream_t s; cudaStreamCreateWithFlags(&s, cudaStreamNonBlocking); return s;
    }();
    static cudaEvent_t evFork = []() {
        cudaEvent_t e; cudaEventCreateWithFlags(&e, cudaEventDisableTiming); return e;
    }();
    static cudaEvent_t evMlp = []() {
        cudaEvent_t e; cudaEventCreateWithFlags(&e, cudaEventDisableTiming); return e;
    }();
    static cudaEvent_t evScores = []() {
        cudaEvent_t e; cudaEventCreateWithFlags(&e, cudaEventDisableTiming); return e;
    }();
    static cudaEvent_t evMean = []() {
        cudaEvent_t e; cudaEventCreateWithFlags(&e, cudaEventDisableTiming); return e;
    }();

    cudaEventRecord(evFork, 0);
    cudaStreamWaitEvent(s1, evFork, 0);
    k_colmean<<<dim3(8, B_, 2), 256, 0, s1>>>(query, key);
    k_mlp<<<B_, 256, 0, s1>>>(Wp1, bp1, Wp2, bp2, Wp3, bp3, out);
    cudaEventRecord(evMlp, s1);

    k_cvt_w<<<2304, 256>>>(in_proj_w, out_w);
    k_qkv_hmma<<<dim3(6, 160), 256>>>(query, key, value, in_proj_b);
    k_scores_pv<<<dim3(8, BH_), 256, SMEM_FUSED>>>(mask);
    cudaEventRecord(evScores, 0);

    cudaStreamWaitEvent(s1, evScores, 0);
    k_meanheads<<<(B_ * LQ * LK / 8) / 256, 256, 0, s1>>>(out);
    cudaEventRecord(evMean, s1);

    k_outproj_hmma<<<dim3(6, 32), 256>>>(out_b);
    cudaStreamWaitEvent(0, evMlp, 0);
    k_final<<<B_ * LQ, 256>>>(query, ln_g, ln_b, out);
    cudaStreamWaitEvent(0, evMean, 0);
}

// round 12
// speedup vs baseline: 2.6188x; 2.6188x over previous
#include <cuda_runtime.h>
#include <cuda_fp16.h>
#include <math.h>
#include <stdint.h>

#define B_   4
#define LQ   1024
#define LK   2048
#define E_   768
#define H_   16
#define HD_  48
#define BH_  (B_*H_)

// ---------------- scratch (device globals) ----------------
__device__ __half g_qh[BH_*LQ*HD_];                // fp16 q  [b][h][lq][d]
__device__ __half g_kh[BH_*LK*HD_];                // fp16 k
__device__ __half g_vh[BH_*LK*HD_];                // fp16 v
__device__ __half g_wh[3*E_*E_];                   // fp16 in_proj_w
__device__ __half g_owh[E_*E_];                    // fp16 out_w
__device__ __half g_s[(size_t)BH_*LQ*LK];          // exp(scores) fp16, unnormalized (268MB)
__device__ float  g_linv[BH_*LQ];                  // 1/rowsum (fp32)
__device__ __half g_ctxh[B_*LQ*E_];                // context fp16
__device__ float  g_ao[B_*LQ*E_];                  // attn_output fp32
__device__ float  g_pin_part[B_*8*1536];
__device__ float  g_gate[B_*3];

// output layout: output | attn_weights | num_heads | scale_factor | gate_value
#define OUT_ATTN ((size_t)B_*LQ*E_)
#define OUT_NH   (OUT_ATTN + (size_t)B_*LQ*LK)
#define OUT_SF   (OUT_NH + 4)
#define OUT_GV   (OUT_SF + 4)

// ---------------- helpers ----------------
__device__ __forceinline__ float fast_exp2(float x) {
    x = fmaxf(x, -120.0f);
    float k = rintf(x);
    float f = x - k;
    float p = 1.33336498e-3f;
    p = fmaf(p, f, 9.61011940e-3f);
    p = fmaf(p, f, 5.55041086e-2f);
    p = fmaf(p, f, 2.40226507e-1f);
    p = fmaf(p, f, 6.93147182e-1f);
    p = fmaf(p, f, 1.0f);
    int ik = (int)k;
    return p * __int_as_float((ik + 127) << 23);
}

__device__ __forceinline__ uint32_t smem_u32(const void* p) {
    uint32_t a;
    asm("{ .reg .u64 t; cvta.to.shared.u64 t, %1; cvt.u32.u64 %0, t; }" : "=r"(a) : "l"(p));
    return a;
}

__device__ __forceinline__ void ldsm_x4(uint32_t& r0, uint32_t& r1, uint32_t& r2, uint32_t& r3, uint32_t addr) {
    asm volatile("ldmatrix.sync.aligned.m8n8.x4.shared.b16 {%0,%1,%2,%3}, [%4];"
                 : "=r"(r0), "=r"(r1), "=r"(r2), "=r"(r3) : "r"(addr));
}
__device__ __forceinline__ void ldsm_x4_t(uint32_t& r0, uint32_t& r1, uint32_t& r2, uint32_t& r3, uint32_t addr) {
    asm volatile("ldmatrix.sync.aligned.m8n8.x4.trans.shared.b16 {%0,%1,%2,%3}, [%4];"
                 : "=r"(r0), "=r"(r1), "=r"(r2), "=r"(r3) : "r"(addr));
}
__device__ __forceinline__ void ldsm_x2(uint32_t& r0, uint32_t& r1, uint32_t addr) {
    asm volatile("ldmatrix.sync.aligned.m8n8.x2.shared.b16 {%0,%1}, [%2];"
                 : "=r"(r0), "=r"(r1) : "r"(addr));
}
__device__ __forceinline__ void mma16816(float c[4], const uint32_t a[4], uint32_t b0, uint32_t b1) {
    asm volatile("mma.sync.aligned.m16n8k16.row.col.f32.f16.f16.f32 "
                 "{%0,%1,%2,%3}, {%4,%5,%6,%7}, {%8,%9}, {%0,%1,%2,%3};"
                 : "+f"(c[0]), "+f"(c[1]), "+f"(c[2]), "+f"(c[3])
                 : "r"(a[0]), "r"(a[1]), "r"(a[2]), "r"(a[3]), "r"(b0), "r"(b1));
}
__device__ __forceinline__ void cp_async16(uint32_t dst, const void* src) {
    asm volatile("cp.async.cg.shared.global [%0], [%1], 16;" :: "r"(dst), "l"(src));
}
__device__ __forceinline__ void cp_commit() { asm volatile("cp.async.commit_group;"); }
__device__ __forceinline__ void cp_wait0()  { asm volatile("cp.async.wait_group 0;" ::: "memory"); }
__device__ __forceinline__ void stcs32(void* p, uint32_t v) {
    asm volatile("st.global.cs.b32 [%0], %1;" :: "l"(p), "r"(v));
}

__device__ __forceinline__ float block_reduce_sum(float v, float* red) {
    int tid = threadIdx.x;
    #pragma unroll
    for (int o = 16; o > 0; o >>= 1) v += __shfl_xor_sync(0xffffffffu, v, o);
    if ((tid & 31) == 0) red[tid >> 5] = v;
    __syncthreads();
    if (tid == 0) {
        float s = red[0];
        for (int i = 1; i < (int)(blockDim.x >> 5); i++) s += red[i];
        red[0] = s;
    }
    __syncthreads();
    float r = red[0];
    __syncthreads();
    return r;
}

// ---------------- 0) convert weights to fp16 ----------------
__global__ void k_cvt_w(const float* __restrict__ ipw, const float* __restrict__ ow) {
    int idx = blockIdx.x * 256 + threadIdx.x;
    const int n1 = 3 * E_ * E_ / 4;
    const int n2 = E_ * E_ / 4;
    if (idx < n1) {
        float4 v = ((const float4*)ipw)[idx];
        __half2 h0 = __floats2half2_rn(v.x, v.y);
        __half2 h1 = __floats2half2_rn(v.z, v.w);
        ((uint2*)g_wh)[idx] = make_uint2(*(uint32_t*)&h0, *(uint32_t*)&h1);
    } else if (idx < n1 + n2) {
        int j = idx - n1;
        float4 v = ((const float4*)ow)[j];
        __half2 h0 = __floats2half2_rn(v.x, v.y);
        __half2 h1 = __floats2half2_rn(v.z, v.w);
        ((uint2*)g_owh)[j] = make_uint2(*(uint32_t*)&h0, *(uint32_t*)&h1);
    }
}

// ---------------- 1) column means (partials) ----------------
__global__ void k_colmean(const float* __restrict__ q, const float* __restrict__ k) {
    int ch = blockIdx.x, b = blockIdx.y, which = blockIdx.z;
    const float* src = which ? k : q;
    int L = which ? LK : LQ;
    int rows = L / 8;
    const float* base = src + ((size_t)b * L + (size_t)ch * rows) * E_;
    for (int c = threadIdx.x; c < E_; c += 256) {
        float s = 0.f;
        for (int r = 0; r < rows; r++) s += base[(size_t)r * E_ + c];
        g_pin_part[(b * 8 + ch) * 1536 + which * E_ + c] = s;
    }
}

// ---------------- 2) gate MLP ----------------
__global__ void k_mlp(const float* __restrict__ Wp1, const float* __restrict__ bp1,
                      const float* __restrict__ Wp2, const float* __restrict__ bp2,
                      const float* __restrict__ Wp3, const float* __restrict__ bp3,
                      float* __restrict__ out) {
    __shared__ float pin[1536];
    __shared__ float h1[768];
    __shared__ float h2[384];
    int b = blockIdx.x, tid = threadIdx.x;
    for (int c = tid; c < 1536; c += 256) {
        float s = 0.f;
        for (int ch = 0; ch < 8; ch++) s += g_pin_part[(b * 8 + ch) * 1536 + c];
        pin[c] = s * ((c < 768) ? (1.0f / LQ) : (1.0f / LK));
    }
    __syncthreads();
    for (int o = tid; o < 768; o += 256) {
        const float* w = Wp1 + (size_t)o * 1536;
        float s = bp1[o];
        for (int i = 0; i < 1536; i++) s = fmaf(pin[i], w[i], s);
        h1[o] = fmaxf(s, 0.f);
    }
    __syncthreads();
    for (int o = tid; o < 384; o += 256) {
        const float* w = Wp2 + (size_t)o * 768;
        float s = bp2[o];
        for (int i = 0; i < 768; i++) s = fmaf(h1[i], w[i], s);
        h2[o] = fmaxf(s, 0.f);
    }
    __syncthreads();
    if (tid < 3) {
        const float* w = Wp3 + tid * 384;
        float s = bp3[tid];
        for (int i = 0; i < 384; i++) s = fmaf(h2[i], w[i], s);
        float sig = 1.f / (1.f + __expf(-s));
        if (tid == 0) {
            float nh = rintf(sig * 15.f + 1.f);
            g_gate[b * 3 + 0] = nh;
            out[OUT_NH + b] = nh;
        } else if (tid == 1) {
            float sf = sig * 0.5f + 0.5f;
            g_gate[b * 3 + 1] = sf;
            out[OUT_SF + b] = sf;
        } else {
            g_gate[b * 3 + 2] = sig;
            out[OUT_GV + b] = sig;
        }
    }
}

// ---------------- 3) QKV projection via HMMA ----------------
#define QKLD 40
__global__ void __launch_bounds__(256) k_qkv_hmma(
    const float* __restrict__ query, const float* __restrict__ key,
    const float* __restrict__ value, const float* __restrict__ bias) {
    __shared__ __half sA[2][128 * QKLD];
    __shared__ __half sB[2][128 * QKLD];
    int yt = blockIdx.y;
    int z, tokbase, Lseq;
    const float* src;
    __half* dst;
    if (yt < 32)      { z = 0; src = query; tokbase = yt * 128;        Lseq = LQ; dst = g_qh; }
    else if (yt < 96) { z = 1; src = key;   tokbase = (yt - 32) * 128; Lseq = LK; dst = g_kh; }
    else              { z = 2; src = value; tokbase = (yt - 96) * 128; Lseq = LK; dst = g_vh; }
    int n0 = blockIdx.x * 128;
    const __half* Bw = g_wh + ((size_t)(z * E_ + n0)) * E_;
    int tid = threadIdx.x, lane = tid & 31, warp = tid >> 5;
    int wm = warp >> 1, wn = warp & 1;
    int ar[4], ac4[4];
    #pragma unroll
    for (int i = 0; i < 4; i++) { int f4 = tid + i * 256; ar[i] = f4 >> 3; ac4[i] = f4 & 7; }
    int br[2], bc8[2];
    #pragma unroll
    for (int i = 0; i < 2; i++) { int u4 = tid + i * 256; br[i] = u4 >> 2; bc8[i] = u4 & 3; }
    #pragma unroll
    for (int i = 0; i < 4; i++) {
        float4 v = *(const float4*)(src + (size_t)(tokbase + ar[i]) * E_ + ac4[i] * 4);
        __half2 h0 = __floats2half2_rn(v.x, v.y);
        __half2 h1 = __floats2half2_rn(v.z, v.w);
        *(uint2*)(sA[0] + ar[i] * QKLD + ac4[i] * 4) = make_uint2(*(uint32_t*)&h0, *(uint32_t*)&h1);
    }
    #pragma unroll
    for (int i = 0; i < 2; i++)
        *(uint4*)(sB[0] + br[i] * QKLD + bc8[i] * 8) = *(const uint4*)(Bw + (size_t)br[i] * E_ + bc8[i] * 8);
    __syncthreads();
    float acc[2][8][4];
    #pragma unroll
    for (int mf = 0; mf < 2; mf++)
        #pragma unroll
        for (int nf = 0; nf < 8; nf++)
            #pragma unroll
            for (int q = 0; q < 4; q++) acc[mf][nf][q] = 0.f;
    int buf = 0;
    float4 apf[4];
    uint4 bpf[2];
    for (int kc = 0; kc < 24; kc++) {
        bool more = (kc + 1) < 24;
        if (more) {
            int kb = (kc + 1) * 32;
            #pragma unroll
            for (int i = 0; i < 4; i++)
                apf[i] = *(const float4*)(src + (size_t)(tokbase + ar[i]) * E_ + kb + ac4[i] * 4);
            #pragma unroll
            for (int i = 0; i < 2; i++)
                bpf[i] = *(const uint4*)(Bw + (size_t)br[i] * E_ + kb + bc8[i] * 8);
        }
        #pragma unroll
        for (int ks = 0; ks < 2; ks++) {
            uint32_t a[2][4];
            #pragma unroll
            for (int mf = 0; mf < 2; mf++) {
                uint32_t addr = smem_u32(sA[buf] + (wm * 32 + mf * 16 + (lane & 15)) * QKLD + ks * 16 + (lane >> 4) * 8);
                ldsm_x4(a[mf][0], a[mf][1], a[mf][2], a[mf][3], addr);
            }
            #pragma unroll
            for (int nf = 0; nf < 8; nf++) {
                uint32_t b0, b1;
                uint32_t addr = smem_u32(sB[buf] + (wn * 64 + nf * 8 + (lane & 7)) * QKLD + ks * 16 + ((lane >> 3) & 1) * 8);
                ldsm_x2(b0, b1, addr);
                mma16816(acc[0][nf], a[0], b0, b1);
                mma16816(acc[1][nf], a[1], b0, b1);
            }
        }
        if (more) {
            int nb = buf ^ 1;
            #pragma unroll
            for (int i = 0; i < 4; i++) {
                __half2 h0 = __floats2half2_rn(apf[i].x, apf[i].y);
                __half2 h1 = __floats2half2_rn(apf[i].z, apf[i].w);
                *(uint2*)(sA[nb] + ar[i] * QKLD + ac4[i] * 4) = make_uint2(*(uint32_t*)&h0, *(uint32_t*)&h1);
            }
            #pragma unroll
            for (int i = 0; i < 2; i++)
                *(uint4*)(sB[nb] + br[i] * QKLD + bc8[i] * 8) = bpf[i];
            __syncthreads();
            buf = nb;
        }
    }
    int bb = tokbase / Lseq;
    int sbase = tokbase % Lseq;
    #pragma unroll
    for (int mf = 0; mf < 2; mf++) {
        int r0 = wm * 32 + mf * 16 + (lane >> 2);
        #pragma unroll
        for (int nf = 0; nf < 8; nf++) {
            int c0 = n0 + wn * 64 + nf * 8 + 2 * (lane & 3);
            int h = c0 / HD_, d = c0 % HD_;
            float bv0 = bias[z * E_ + c0], bv1 = bias[z * E_ + c0 + 1];
            size_t a0 = (((size_t)(bb * H_ + h)) * Lseq + sbase + r0) * HD_ + d;
            size_t a1 = (((size_t)(bb * H_ + h)) * Lseq + sbase + r0 + 8) * HD_ + d;
            *(__half2*)(dst + a0) = __floats2half2_rn(acc[mf][nf][0] + bv0, acc[mf][nf][1] + bv1);
            *(__half2*)(dst + a1) = __floats2half2_rn(acc[mf][nf][2] + bv0, acc[mf][nf][3] + bv1);
        }
    }
}

// ------- 4) FUSED scores+PV: cp.async K/V pipeline, 64-col halves.
//         NO forced min-blocks (R10's cap caused register spills). -------
#define SQLD 56
#define VLD  56
static constexpr int SMEM_FUSED =
    (128 * SQLD + 2 * 128 * SQLD + 2 * 128 * VLD) * 2 + LK * 4;   // 79872 B
__global__ void __launch_bounds__(256) k_scores_pv(const unsigned char* __restrict__ mask) {
    extern __shared__ __align__(16) char smem_raw[];
    __half* sQ = (__half*)smem_raw;                        // 128*SQLD
    __half* sK = sQ + 128 * SQLD;                          // 2 x 128*SQLD
    __half* sV = sK + 2 * 128 * SQLD;                      // 2 x 128*VLD
    float*  sMsk = (float*)(sV + 2 * 128 * VLD);           // LK
    int bh = blockIdx.y, m0 = blockIdx.x * 128, b = bh >> 4;
    int tid = threadIdx.x, lane = tid & 31, w = tid >> 5;
    const __half* Qsrc = g_qh + ((size_t)bh * LQ + m0) * HD_;
    const __half* Ksrc = g_kh + (size_t)bh * LK * HD_;
    const __half* Vsrc = g_vh + (size_t)bh * LK * HD_;
    // stage Q (768 uint4) + mask
    #pragma unroll
    for (int i = 0; i < 3; i++) {
        int idx = tid + i * 256;
        int r = idx / 6, c8 = idx % 6;
        *(uint4*)(sQ + r * SQLD + c8 * 8) = *(const uint4*)(Qsrc + (size_t)r * HD_ + c8 * 8);
    }
    #pragma unroll
    for (int i = 0; i < 8; i++) {
        int c = tid + i * 256;
        sMsk[c] = mask[b * LK + c] ? 0.f : 1.f;
    }
    // cp.async K,V tile 0
    int rr[3], cc[3];
    #pragma unroll
    for (int i = 0; i < 3; i++) { int idx = tid + i * 256; rr[i] = idx / 6; cc[i] = idx % 6; }
    #pragma unroll
    for (int i = 0; i < 3; i++) {
        cp_async16(smem_u32(sK + rr[i] * SQLD + cc[i] * 8), Ksrc + (size_t)rr[i] * HD_ + cc[i] * 8);
        cp_async16(smem_u32(sV + rr[i] * VLD + cc[i] * 8),  Vsrc + (size_t)rr[i] * HD_ + cc[i] * 8);
    }
    cp_commit();
    cp_wait0();
    __syncthreads();
    // Q fragments: warp rows w*16..+16, 3 k16 steps
    uint32_t aQ[3][4];
    #pragma unroll
    for (int ks = 0; ks < 3; ks++) {
        uint32_t addr = smem_u32(sQ + (w * 16 + (lane & 15)) * SQLD + ks * 16 + (lane >> 4) * 8);
        ldsm_x4(aQ[ks][0], aQ[ks][1], aQ[ks][2], aQ[ks][3], addr);
    }
    float rsum[2] = {0.f, 0.f};
    float acc_o[6][4];
    #pragma unroll
    for (int nfv = 0; nfv < 6; nfv++)
        #pragma unroll
        for (int q = 0; q < 4; q++) acc_o[nfv][q] = 0.f;
    __half* srow = g_s + (size_t)bh * LQ * LK;
    const float cs = 0.14433757f * 1.44269504f;
    int lr0 = w * 16 + (lane >> 2);
    int buf = 0;
    for (int t = 0; t < 16; t++) {
        bool more = (t + 1) < 16;
        if (more) {
            const __half* Kn = Ksrc + (size_t)(t + 1) * 128 * HD_;
            const __half* Vn = Vsrc + (size_t)(t + 1) * 128 * HD_;
            int nb = buf ^ 1;
            #pragma unroll
            for (int i = 0; i < 3; i++) {
                cp_async16(smem_u32(sK + nb * 128 * SQLD + rr[i] * SQLD + cc[i] * 8),
                           Kn + (size_t)rr[i] * HD_ + cc[i] * 8);
                cp_async16(smem_u32(sV + nb * 128 * VLD + rr[i] * VLD + cc[i] * 8),
                           Vn + (size_t)rr[i] * HD_ + cc[i] * 8);
            }
            cp_commit();
        }
        #pragma unroll
        for (int hf = 0; hf < 2; hf++) {
            // QK: this warp's 16 rows x 64 cols
            float acc[8][4];
            #pragma unroll
            for (int nf = 0; nf < 8; nf++)
                #pragma unroll
                for (int q = 0; q < 4; q++) acc[nf][q] = 0.f;
            #pragma unroll
            for (int ks = 0; ks < 3; ks++) {
                #pragma unroll
                for (int nfp = 0; nfp < 4; nfp++) {
                    uint32_t m0r, m1r, m2r, m3r;
                    uint32_t addr = smem_u32(sK + buf * 128 * SQLD +
                                             (hf * 64 + nfp * 16 + (lane & 15)) * SQLD + ks * 16 + (lane >> 4) * 8);
                    ldsm_x4(m0r, m1r, m2r, m3r, addr);
                    mma16816(acc[2 * nfp],     aQ[ks], m0r, m2r);
                    mma16816(acc[2 * nfp + 1], aQ[ks], m1r, m3r);
                }
            }
            // epilogue: exp, mask, rowsum, store fp16 (.cs), pack A-frags
            int n0 = t * 128 + hf * 64;
            uint32_t ph01[8], ph23[8];
            #pragma unroll
            for (int nf = 0; nf < 8; nf++) {
                int c = n0 + nf * 8 + 2 * (lane & 3);
                float mk0 = sMsk[c], mk1 = sMsk[c + 1];
                float p00 = fast_exp2(acc[nf][0] * cs) * mk0;
                float p01 = fast_exp2(acc[nf][1] * cs) * mk1;
                float p10 = fast_exp2(acc[nf][2] * cs) * mk0;
                float p11 = fast_exp2(acc[nf][3] * cs) * mk1;
                rsum[0] += p00 + p01;
                rsum[1] += p10 + p11;
                __half2 h0 = __floats2half2_rn(p00, p01);
                __half2 h1 = __floats2half2_rn(p10, p11);
                ph01[nf] = *(uint32_t*)&h0;
                ph23[nf] = *(uint32_t*)&h1;
                stcs32(srow + (size_t)(m0 + lr0) * LK + c,     ph01[nf]);
                stcs32(srow + (size_t)(m0 + lr0 + 8) * LK + c, ph23[nf]);
            }
            // PV: ctx += P_half(16x64) @ V_half(64x48)
            #pragma unroll
            for (int ksl = 0; ksl < 4; ksl++) {
                uint32_t pA[4] = {ph01[2 * ksl], ph23[2 * ksl], ph01[2 * ksl + 1], ph23[2 * ksl + 1]};
                #pragma unroll
                for (int nfvp = 0; nfvp < 3; nfvp++) {
                    uint32_t v0, v1, v2, v3;
                    uint32_t addr = smem_u32(sV + buf * 128 * VLD +
                                             (hf * 64 + ksl * 16 + (lane & 15)) * VLD + nfvp * 16 + (lane >> 4) * 8);
                    ldsm_x4_t(v0, v1, v2, v3, addr);
                    mma16816(acc_o[2 * nfvp],     pA, v0, v1);
                    mma16816(acc_o[2 * nfvp + 1], pA, v2, v3);
                }
            }
        }
        if (more) {
            cp_wait0();
            __syncthreads();
            buf ^= 1;
        }
    }
    // row sums: reduce over quad lanes (cols)
    #pragma unroll
    for (int r = 0; r < 2; r++) {
        rsum[r] += __shfl_xor_sync(0xffffffffu, rsum[r], 1);
        rsum[r] += __shfl_xor_sync(0xffffffffu, rsum[r], 2);
    }
    float linv0 = 1.0f / rsum[0];
    float linv1 = 1.0f / rsum[1];
    if ((lane & 3) == 0) {
        g_linv[bh * LQ + m0 + lr0]     = linv0;
        g_linv[bh * LQ + m0 + lr0 + 8] = linv1;
    }
    // write ctx (fp16, per-token layout)
    int h = bh & 15;
    #pragma unroll
    for (int nfv = 0; nfv < 6; nfv++) {
        int d = nfv * 8 + 2 * (lane & 3);
        __half* dst0 = g_ctxh + ((size_t)b * LQ + m0 + lr0) * E_ + h * HD_ + d;
        __half* dst1 = g_ctxh + ((size_t)b * LQ + m0 + lr0 + 8) * E_ + h * HD_ + d;
        *(__half2*)dst0 = __floats2half2_rn(acc_o[nfv][0] * linv0, acc_o[nfv][1] * linv0);
        *(__half2*)dst1 = __floats2half2_rn(acc_o[nfv][2] * linv1, acc_o[nfv][3] * linv1);
    }
}

// ---------------- 6) attn_weights = mean over heads (normalized), fp16 streaming reads ----------------
__global__ void __launch_bounds__(256) k_meanheads(float* __restrict__ out) {
    size_t idx8 = (size_t)blockIdx.x * 256 + threadIdx.x;
    const size_t per_b8 = (size_t)LQ * LK / 8;
    int b = (int)(idx8 / per_b8);
    size_t rem8 = idx8 % per_b8;
    int q = (int)(rem8 >> 8);
    const uint4* base = (const uint4*)g_s + (size_t)b * H_ * per_b8 + rem8;
    float acc[8];
    #pragma unroll
    for (int j = 0; j < 8; j++) acc[j] = 0.f;
    #pragma unroll
    for (int h = 0; h < H_; h++) {
        float inv = g_linv[(b * H_ + h) * LQ + q];
        uint4 v = __ldcs(base + (size_t)h * per_b8);
        __half2* hh = (__half2*)&v;
        #pragma unroll
        for (int j = 0; j < 4; j++) {
            float2 f = __half22float2(hh[j]);
            acc[2 * j + 0] = fmaf(f.x, inv, acc[2 * j + 0]);
            acc[2 * j + 1] = fmaf(f.y, inv, acc[2 * j + 1]);
        }
    }
    const float ih = 1.0f / H_;
    float* dst = out + OUT_ATTN + idx8 * 8;
    *(float4*)(dst)     = make_float4(acc[0] * ih, acc[1] * ih, acc[2] * ih, acc[3] * ih);
    *(float4*)(dst + 4) = make_float4(acc[4] * ih, acc[5] * ih, acc[6] * ih, acc[7] * ih);
}

// ---------------- 8) attn_output = ctx @ out_w^T + out_b via HMMA ----------------
__global__ void __launch_bounds__(256) k_outproj_hmma(const float* __restrict__ out_b) {
    __shared__ __half sA[2][128 * QKLD];
    __shared__ __half sB[2][128 * QKLD];
    int m0 = blockIdx.y * 128, n0 = blockIdx.x * 128;
    int tid = threadIdx.x, lane = tid & 31, warp = tid >> 5;
    int wm = warp >> 1, wn = warp & 1;
    const __half* Asrc = g_ctxh + (size_t)m0 * E_;
    const __half* Bw = g_owh + (size_t)n0 * E_;
    int ur[2], uc8[2];
    #pragma unroll
    for (int i = 0; i < 2; i++) { int u4 = tid + i * 256; ur[i] = u4 >> 2; uc8[i] = u4 & 3; }
    #pragma unroll
    for (int i = 0; i < 2; i++) {
        *(uint4*)(sA[0] + ur[i] * QKLD + uc8[i] * 8) = *(const uint4*)(Asrc + (size_t)ur[i] * E_ + uc8[i] * 8);
        *(uint4*)(sB[0] + ur[i] * QKLD + uc8[i] * 8) = *(const uint4*)(Bw + (size_t)ur[i] * E_ + uc8[i] * 8);
    }
    __syncthreads();
    float acc[2][8][4];
    #pragma unroll
    for (int mf = 0; mf < 2; mf++)
        #pragma unroll
        for (int nf = 0; nf < 8; nf++)
            #pragma unroll
            for (int q = 0; q < 4; q++) acc[mf][nf][q] = 0.f;
    int buf = 0;
    uint4 apf[2], bpf[2];
    for (int kc = 0; kc < 24; kc++) {
        bool more = (kc + 1) < 24;
        if (more) {
            int kb = (kc + 1) * 32;
            #pragma unroll
            for (int i = 0; i < 2; i++) {
                apf[i] = *(const uint4*)(Asrc + (size_t)ur[i] * E_ + kb + uc8[i] * 8);
                bpf[i] = *(const uint4*)(Bw + (size_t)ur[i] * E_ + kb + uc8[i] * 8);
            }
        }
        #pragma unroll
        for (int ks = 0; ks < 2; ks++) {
            uint32_t a[2][4];
            #pragma unroll
            for (int mf = 0; mf < 2; mf++) {
                uint32_t addr = smem_u32(sA[buf] + (wm * 32 + mf * 16 + (lane & 15)) * QKLD + ks * 16 + (lane >> 4) * 8);
                ldsm_x4(a[mf][0], a[mf][1], a[mf][2], a[mf][3], addr);
            }
            #pragma unroll
            for (int nf = 0; nf < 8; nf++) {
                uint32_t b0, b1;
                uint32_t addr = smem_u32(sB[buf] + (wn * 64 + nf * 8 + (lane & 7)) * QKLD + ks * 16 + ((lane >> 3) & 1) * 8);
                ldsm_x2(b0, b1, addr);
                mma16816(acc[0][nf], a[0], b0, b1);
                mma16816(acc[1][nf], a[1], b0, b1);
            }
        }
        if (more) {
            int nb = buf ^ 1;
            #pragma unroll
            for (int i = 0; i < 2; i++) {
                *(uint4*)(sA[nb] + ur[i] * QKLD + uc8[i] * 8) = apf[i];
                *(uint4*)(sB[nb] + ur[i] * QKLD + uc8[i] * 8) = bpf[i];
            }
            __syncthreads();
            buf = nb;
        }
    }
    #pragma unroll
    for (int mf = 0; mf < 2; mf++) {
        int r0 = m0 + wm * 32 + mf * 16 + (lane >> 2);
        #pragma unroll
        for (int nf = 0; nf < 8; nf++) {
            int c0 = n0 + wn * 64 + nf * 8 + 2 * (lane & 3);
            float bv0 = out_b[c0], bv1 = out_b[c0 + 1];
            *(float2*)(g_ao + (size_t)r0 * E_ + c0)       = make_float2(acc[mf][nf][0] + bv0, acc[mf][nf][1] + bv1);
            *(float2*)(g_ao + (size_t)(r0 + 8) * E_ + c0) = make_float2(acc[mf][nf][2] + bv0, acc[mf][nf][3] + bv1);
        }
    }
}

// ---------------- 9) gate + residual + layernorm ----------------
__global__ void __launch_bounds__(256) k_final(const float* __restrict__ query,
                                               const float* __restrict__ ln_g,
                                               const float* __restrict__ ln_b,
                                               float* __restrict__ out) {
    __shared__ float xs[768];
    __shared__ float red[8];
    int t = blockIdx.x;
    int b = t >> 10;
    float sf = g_gate[b * 3 + 1], gv = g_gate[b * 3 + 2];
    const float* qrow = query + (size_t)t * E_;
    const float* arow = g_ao + (size_t)t * E_;
    int tid = threadIdx.x;
    float lsum = 0.f;
    for (int c = tid; c < E_; c += 256) {
        float q = qrow[c], a = arow[c];
        float gated = q * (1.f - gv) + a * sf * gv;
        float x = q + gated;
        xs[c] = x;
        lsum += x;
    }
    float mu = block_reduce_sum(lsum, red) * (1.0f / E_);
    float lv = 0.f;
    for (int c = tid; c < E_; c += 256) {
        float d = xs[c] - mu;
        lv += d * d;
    }
    float var = block_reduce_sum(lv, red) * (1.0f / E_);
    float inv = rsqrtf(var + 1e-5f);
    for (int c = tid; c < E_; c += 256)
        out[(size_t)t * E_ + c] = (xs[c] - mu) * inv * ln_g[c] + ln_b[c];
}

// ---------------- launcher (multi-stream fork/join, capture-safe) ----------------
extern "C" void kernel_launch(void* const* d_in, const int* in_sizes, int n_in,
                              void* d_out, int out_size) {
    const float* query = (const float*)d_in[0];
    const float* key   = (const float*)d_in[1];
    const float* value = (const float*)d_in[2];
    const unsigned char* mask = (const unsigned char*)d_in[3];
    const float* Wp1 = (const float*)d_in[4];
    const float* bp1 = (const float*)d_in[5];
    const float* Wp2 = (const float*)d_in[6];
    const float* bp2 = (const float*)d_in[7];
    const float* Wp3 = (const float*)d_in[8];
    const float* bp3 = (const float*)d_in[9];
    const float* in_proj_w = (const float*)d_in[10];
    const float* in_proj_b = (const float*)d_in[11];
    const float* out_w = (const float*)d_in[12];
    const float* out_b = (const float*)d_in[13];
    const float* ln_g  = (const float*)d_in[14];
    const float* ln_b  = (const float*)d_in[15];
    float* out = (float*)d_out;

    static bool once = []() {
        cudaFuncSetAttribute(k_scores_pv, cudaFuncAttributeMaxDynamicSharedMemorySize, SMEM_FUSED);
        return true;
    }();
    (void)once;

    static cudaStream_t s1 = []() {
        cudaStream_t s; cudaStreamCreateWithFlags(&s, cudaStreamNonBlocking); return s;
    }();
    static cudaEvent_t evFork = []() {
        cudaEvent_t e; cudaEventCreateWithFlags(&e, cudaEventDisableTiming); return e;
    }();
    static cudaEvent_t evMlp = []() {
        cudaEvent_t e; cudaEventCreateWithFlags(&e, cudaEventDisableTiming); return e;
    }();
    static cudaEvent_t evScores = []() {
        cudaEvent_t e; cudaEventCreateWithFlags(&e, cudaEventDisableTiming); return e;
    }();
    static cudaEvent_t evMean = []() {
        cudaEvent_t e; cudaEventCreateWithFlags(&e, cudaEventDisableTiming); return e;
    }();

    cudaEventRecord(evFork, 0);
    cudaStreamWaitEvent(s1, evFork, 0);
    k_colmean<<<dim3(8, B_, 2), 256, 0, s1>>>(query, key);
    k_mlp<<<B_, 256, 0, s1>>>(Wp1, bp1, Wp2, bp2, Wp3, bp3, out);
    cudaEventRecord(evMlp, s1);

    k_cvt_w<<<2304, 256>>>(in_proj_w, out_w);
    k_qkv_hmma<<<dim3(6, 160), 256>>>(query, key, value, in_proj_b);
    k_scores_pv<<<dim3(8, BH_), 256, SMEM_FUSED>>>(mask);
    cudaEventRecord(evScores, 0);

    cudaStreamWaitEvent(s1, evScores, 0);
    k_meanheads<<<(B_ * LQ * LK / 8) / 256, 256, 0, s1>>>(out);
    cudaEventRecord(evMean, s1);

    k_outproj_hmma<<<dim3(6, 32), 256>>>(out_b);
    cudaStreamWaitEvent(0, evMlp, 0);
    k_final<<<B_ * LQ, 256>>>(query, ln_g, ln_b, out);
    cudaStreamWaitEvent(0, evMean, 0);
}

// round 14
// speedup vs baseline: 2.8219x; 1.0775x over previous
#include <cuda_runtime.h>
#include <cuda_fp16.h>
#include <math.h>
#include <stdint.h>

#define B_   4
#define LQ   1024
#define LK   2048
#define E_   768
#define H_   16
#define HD_  48
#define BH_  (B_*H_)

// ---------------- scratch (device globals) ----------------
__device__ __half g_qh[BH_*LQ*HD_];                // fp16 q  [b][h][lq][d]
__device__ __half g_kh[BH_*LK*HD_];                // fp16 k
__device__ __half g_vh[BH_*LK*HD_];                // fp16 v
__device__ __half g_wh[3*E_*E_];                   // fp16 in_proj_w
__device__ __half g_owh[E_*E_];                    // fp16 out_w
__device__ __half g_s[(size_t)BH_*LQ*LK];          // exp(scores) fp16, unnormalized (268MB)
__device__ float  g_linv[BH_*LQ];                  // 1/rowsum (fp32)
__device__ __half g_ctxh[B_*LQ*E_];                // context fp16
__device__ float  g_ao[B_*LQ*E_];                  // attn_output fp32
__device__ float  g_pin_part[B_*8*1536];
__device__ float  g_gate[B_*3];

// output layout: output | attn_weights | num_heads | scale_factor | gate_value
#define OUT_ATTN ((size_t)B_*LQ*E_)
#define OUT_NH   (OUT_ATTN + (size_t)B_*LQ*LK)
#define OUT_SF   (OUT_NH + 4)
#define OUT_GV   (OUT_SF + 4)

// ---------------- helpers ----------------
__device__ __forceinline__ float fast_exp2(float x) {
    x = fmaxf(x, -120.0f);
    float k = rintf(x);
    float f = x - k;
    float p = 1.33336498e-3f;
    p = fmaf(p, f, 9.61011940e-3f);
    p = fmaf(p, f, 5.55041086e-2f);
    p = fmaf(p, f, 2.40226507e-1f);
    p = fmaf(p, f, 6.93147182e-1f);
    p = fmaf(p, f, 1.0f);
    int ik = (int)k;
    return p * __int_as_float((ik + 127) << 23);
}

__device__ __forceinline__ uint32_t smem_u32(const void* p) {
    uint32_t a;
    asm("{ .reg .u64 t; cvta.to.shared.u64 t, %1; cvt.u32.u64 %0, t; }" : "=r"(a) : "l"(p));
    return a;
}

__device__ __forceinline__ void ldsm_x4(uint32_t& r0, uint32_t& r1, uint32_t& r2, uint32_t& r3, uint32_t addr) {
    asm volatile("ldmatrix.sync.aligned.m8n8.x4.shared.b16 {%0,%1,%2,%3}, [%4];"
                 : "=r"(r0), "=r"(r1), "=r"(r2), "=r"(r3) : "r"(addr));
}
__device__ __forceinline__ void ldsm_x4_t(uint32_t& r0, uint32_t& r1, uint32_t& r2, uint32_t& r3, uint32_t addr) {
    asm volatile("ldmatrix.sync.aligned.m8n8.x4.trans.shared.b16 {%0,%1,%2,%3}, [%4];"
                 : "=r"(r0), "=r"(r1), "=r"(r2), "=r"(r3) : "r"(addr));
}
__device__ __forceinline__ void ldsm_x2(uint32_t& r0, uint32_t& r1, uint32_t addr) {
    asm volatile("ldmatrix.sync.aligned.m8n8.x2.shared.b16 {%0,%1}, [%2];"
                 : "=r"(r0), "=r"(r1) : "r"(addr));
}
__device__ __forceinline__ void mma16816(float c[4], const uint32_t a[4], uint32_t b0, uint32_t b1) {
    asm volatile("mma.sync.aligned.m16n8k16.row.col.f32.f16.f16.f32 "
                 "{%0,%1,%2,%3}, {%4,%5,%6,%7}, {%8,%9}, {%0,%1,%2,%3};"
                 : "+f"(c[0]), "+f"(c[1]), "+f"(c[2]), "+f"(c[3])
                 : "r"(a[0]), "r"(a[1]), "r"(a[2]), "r"(a[3]), "r"(b0), "r"(b1));
}
__device__ __forceinline__ void cp_async16(uint32_t dst, const void* src) {
    asm volatile("cp.async.cg.shared.global [%0], [%1], 16;" :: "r"(dst), "l"(src));
}
__device__ __forceinline__ void cp_commit() { asm volatile("cp.async.commit_group;"); }
__device__ __forceinline__ void cp_wait0()  { asm volatile("cp.async.wait_group 0;" ::: "memory"); }
__device__ __forceinline__ void stcs32(void* p, uint32_t v) {
    asm volatile("st.global.cs.b32 [%0], %1;" :: "l"(p), "r"(v));
}

__device__ __forceinline__ float block_reduce_sum(float v, float* red) {
    int tid = threadIdx.x;
    #pragma unroll
    for (int o = 16; o > 0; o >>= 1) v += __shfl_xor_sync(0xffffffffu, v, o);
    if ((tid & 31) == 0) red[tid >> 5] = v;
    __syncthreads();
    if (tid == 0) {
        float s = red[0];
        for (int i = 1; i < (int)(blockDim.x >> 5); i++) s += red[i];
        red[0] = s;
    }
    __syncthreads();
    float r = red[0];
    __syncthreads();
    return r;
}

// ---------------- 0) convert weights to fp16 ----------------
__global__ void k_cvt_w(const float* __restrict__ ipw, const float* __restrict__ ow) {
    int idx = blockIdx.x * 256 + threadIdx.x;
    const int n1 = 3 * E_ * E_ / 4;
    const int n2 = E_ * E_ / 4;
    if (idx < n1) {
        float4 v = ((const float4*)ipw)[idx];
        __half2 h0 = __floats2half2_rn(v.x, v.y);
        __half2 h1 = __floats2half2_rn(v.z, v.w);
        ((uint2*)g_wh)[idx] = make_uint2(*(uint32_t*)&h0, *(uint32_t*)&h1);
    } else if (idx < n1 + n2) {
        int j = idx - n1;
        float4 v = ((const float4*)ow)[j];
        __half2 h0 = __floats2half2_rn(v.x, v.y);
        __half2 h1 = __floats2half2_rn(v.z, v.w);
        ((uint2*)g_owh)[j] = make_uint2(*(uint32_t*)&h0, *(uint32_t*)&h1);
    }
}

// ---------------- 1) column means (partials) ----------------
__global__ void k_colmean(const float* __restrict__ q, const float* __restrict__ k) {
    int ch = blockIdx.x, b = blockIdx.y, which = blockIdx.z;
    const float* src = which ? k : q;
    int L = which ? LK : LQ;
    int rows = L / 8;
    const float* base = src + ((size_t)b * L + (size_t)ch * rows) * E_;
    for (int c = threadIdx.x; c < E_; c += 256) {
        float s = 0.f;
        for (int r = 0; r < rows; r++) s += base[(size_t)r * E_ + c];
        g_pin_part[(b * 8 + ch) * 1536 + which * E_ + c] = s;
    }
}

// ---------------- 2) gate MLP ----------------
__global__ void k_mlp(const float* __restrict__ Wp1, const float* __restrict__ bp1,
                      const float* __restrict__ Wp2, const float* __restrict__ bp2,
                      const float* __restrict__ Wp3, const float* __restrict__ bp3,
                      float* __restrict__ out) {
    __shared__ float pin[1536];
    __shared__ float h1[768];
    __shared__ float h2[384];
    int b = blockIdx.x, tid = threadIdx.x;
    for (int c = tid; c < 1536; c += 256) {
        float s = 0.f;
        for (int ch = 0; ch < 8; ch++) s += g_pin_part[(b * 8 + ch) * 1536 + c];
        pin[c] = s * ((c < 768) ? (1.0f / LQ) : (1.0f / LK));
    }
    __syncthreads();
    for (int o = tid; o < 768; o += 256) {
        const float* w = Wp1 + (size_t)o * 1536;
        float s = bp1[o];
        for (int i = 0; i < 1536; i++) s = fmaf(pin[i], w[i], s);
        h1[o] = fmaxf(s, 0.f);
    }
    __syncthreads();
    for (int o = tid; o < 384; o += 256) {
        const float* w = Wp2 + (size_t)o * 768;
        float s = bp2[o];
        for (int i = 0; i < 768; i++) s = fmaf(h1[i], w[i], s);
        h2[o] = fmaxf(s, 0.f);
    }
    __syncthreads();
    if (tid < 3) {
        const float* w = Wp3 + tid * 384;
        float s = bp3[tid];
        for (int i = 0; i < 384; i++) s = fmaf(h2[i], w[i], s);
        float sig = 1.f / (1.f + __expf(-s));
        if (tid == 0) {
            float nh = rintf(sig * 15.f + 1.f);
            g_gate[b * 3 + 0] = nh;
            out[OUT_NH + b] = nh;
        } else if (tid == 1) {
            float sf = sig * 0.5f + 0.5f;
            g_gate[b * 3 + 1] = sf;
            out[OUT_SF + b] = sf;
        } else {
            g_gate[b * 3 + 2] = sig;
            out[OUT_GV + b] = sig;
        }
    }
}

// ---------------- 3) QKV projection via HMMA ----------------
#define QKLD 40
__global__ void __launch_bounds__(256) k_qkv_hmma(
    const float* __restrict__ query, const float* __restrict__ key,
    const float* __restrict__ value, const float* __restrict__ bias) {
    __shared__ __half sA[2][128 * QKLD];
    __shared__ __half sB[2][128 * QKLD];
    int yt = blockIdx.y;
    int z, tokbase, Lseq;
    const float* src;
    __half* dst;
    if (yt < 32)      { z = 0; src = query; tokbase = yt * 128;        Lseq = LQ; dst = g_qh; }
    else if (yt < 96) { z = 1; src = key;   tokbase = (yt - 32) * 128; Lseq = LK; dst = g_kh; }
    else              { z = 2; src = value; tokbase = (yt - 96) * 128; Lseq = LK; dst = g_vh; }
    int n0 = blockIdx.x * 128;
    const __half* Bw = g_wh + ((size_t)(z * E_ + n0)) * E_;
    int tid = threadIdx.x, lane = tid & 31, warp = tid >> 5;
    int wm = warp >> 1, wn = warp & 1;
    int ar[4], ac4[4];
    #pragma unroll
    for (int i = 0; i < 4; i++) { int f4 = tid + i * 256; ar[i] = f4 >> 3; ac4[i] = f4 & 7; }
    int br[2], bc8[2];
    #pragma unroll
    for (int i = 0; i < 2; i++) { int u4 = tid + i * 256; br[i] = u4 >> 2; bc8[i] = u4 & 3; }
    #pragma unroll
    for (int i = 0; i < 4; i++) {
        float4 v = *(const float4*)(src + (size_t)(tokbase + ar[i]) * E_ + ac4[i] * 4);
        __half2 h0 = __floats2half2_rn(v.x, v.y);
        __half2 h1 = __floats2half2_rn(v.z, v.w);
        *(uint2*)(sA[0] + ar[i] * QKLD + ac4[i] * 4) = make_uint2(*(uint32_t*)&h0, *(uint32_t*)&h1);
    }
    #pragma unroll
    for (int i = 0; i < 2; i++)
        *(uint4*)(sB[0] + br[i] * QKLD + bc8[i] * 8) = *(const uint4*)(Bw + (size_t)br[i] * E_ + bc8[i] * 8);
    __syncthreads();
    float acc[2][8][4];
    #pragma unroll
    for (int mf = 0; mf < 2; mf++)
        #pragma unroll
        for (int nf = 0; nf < 8; nf++)
            #pragma unroll
            for (int q = 0; q < 4; q++) acc[mf][nf][q] = 0.f;
    int buf = 0;
    float4 apf[4];
    uint4 bpf[2];
    for (int kc = 0; kc < 24; kc++) {
        bool more = (kc + 1) < 24;
        if (more) {
            int kb = (kc + 1) * 32;
            #pragma unroll
            for (int i = 0; i < 4; i++)
                apf[i] = *(const float4*)(src + (size_t)(tokbase + ar[i]) * E_ + kb + ac4[i] * 4);
            #pragma unroll
            for (int i = 0; i < 2; i++)
                bpf[i] = *(const uint4*)(Bw + (size_t)br[i] * E_ + kb + bc8[i] * 8);
        }
        #pragma unroll
        for (int ks = 0; ks < 2; ks++) {
            uint32_t a[2][4];
            #pragma unroll
            for (int mf = 0; mf < 2; mf++) {
                uint32_t addr = smem_u32(sA[buf] + (wm * 32 + mf * 16 + (lane & 15)) * QKLD + ks * 16 + (lane >> 4) * 8);
                ldsm_x4(a[mf][0], a[mf][1], a[mf][2], a[mf][3], addr);
            }
            #pragma unroll
            for (int nf = 0; nf < 8; nf++) {
                uint32_t b0, b1;
                uint32_t addr = smem_u32(sB[buf] + (wn * 64 + nf * 8 + (lane & 7)) * QKLD + ks * 16 + ((lane >> 3) & 1) * 8);
                ldsm_x2(b0, b1, addr);
                mma16816(acc[0][nf], a[0], b0, b1);
                mma16816(acc[1][nf], a[1], b0, b1);
            }
        }
        if (more) {
            int nb = buf ^ 1;
            #pragma unroll
            for (int i = 0; i < 4; i++) {
                __half2 h0 = __floats2half2_rn(apf[i].x, apf[i].y);
                __half2 h1 = __floats2half2_rn(apf[i].z, apf[i].w);
                *(uint2*)(sA[nb] + ar[i] * QKLD + ac4[i] * 4) = make_uint2(*(uint32_t*)&h0, *(uint32_t*)&h1);
            }
            #pragma unroll
            for (int i = 0; i < 2; i++)
                *(uint4*)(sB[nb] + br[i] * QKLD + bc8[i] * 8) = bpf[i];
            __syncthreads();
            buf = nb;
        }
    }
    int bb = tokbase / Lseq;
    int sbase = tokbase % Lseq;
    #pragma unroll
    for (int mf = 0; mf < 2; mf++) {
        int r0 = wm * 32 + mf * 16 + (lane >> 2);
        #pragma unroll
        for (int nf = 0; nf < 8; nf++) {
            int c0 = n0 + wn * 64 + nf * 8 + 2 * (lane & 3);
            int h = c0 / HD_, d = c0 % HD_;
            float bv0 = bias[z * E_ + c0], bv1 = bias[z * E_ + c0 + 1];
            size_t a0 = (((size_t)(bb * H_ + h)) * Lseq + sbase + r0) * HD_ + d;
            size_t a1 = (((size_t)(bb * H_ + h)) * Lseq + sbase + r0 + 8) * HD_ + d;
            *(__half2*)(dst + a0) = __floats2half2_rn(acc[mf][nf][0] + bv0, acc[mf][nf][1] + bv1);
            *(__half2*)(dst + a1) = __floats2half2_rn(acc[mf][nf][2] + bv0, acc[mf][nf][3] + bv1);
        }
    }
}

// ------- 4) FUSED scores+PV: interleaved per-16-col chunk (low register pressure),
//         cp.async K/V pipeline, 2 CTAs/SM. -------
#define SQLD 56
#define VLD  56
static constexpr int SMEM_FUSED =
    (128 * SQLD + 2 * 128 * SQLD + 2 * 128 * VLD) * 2 + LK * 4;   // 79872 B
__global__ void __launch_bounds__(256, 2) k_scores_pv(const unsigned char* __restrict__ mask) {
    extern __shared__ __align__(16) char smem_raw[];
    __half* sQ = (__half*)smem_raw;                        // 128*SQLD
    __half* sK = sQ + 128 * SQLD;                          // 2 x 128*SQLD
    __half* sV = sK + 2 * 128 * SQLD;                      // 2 x 128*VLD
    float*  sMsk = (float*)(sV + 2 * 128 * VLD);           // LK
    int bh = blockIdx.y, m0 = blockIdx.x * 128, b = bh >> 4;
    int tid = threadIdx.x, lane = tid & 31, w = tid >> 5;
    const __half* Qsrc = g_qh + ((size_t)bh * LQ + m0) * HD_;
    const __half* Ksrc = g_kh + (size_t)bh * LK * HD_;
    const __half* Vsrc = g_vh + (size_t)bh * LK * HD_;
    // stage Q (768 uint4) + mask
    #pragma unroll
    for (int i = 0; i < 3; i++) {
        int idx = tid + i * 256;
        int r = idx / 6, c8 = idx % 6;
        *(uint4*)(sQ + r * SQLD + c8 * 8) = *(const uint4*)(Qsrc + (size_t)r * HD_ + c8 * 8);
    }
    #pragma unroll
    for (int i = 0; i < 8; i++) {
        int c = tid + i * 256;
        sMsk[c] = mask[b * LK + c] ? 0.f : 1.f;
    }
    // cp.async K,V tile 0
    int rr[3], cc[3];
    #pragma unroll
    for (int i = 0; i < 3; i++) { int idx = tid + i * 256; rr[i] = idx / 6; cc[i] = idx % 6; }
    #pragma unroll
    for (int i = 0; i < 3; i++) {
        cp_async16(smem_u32(sK + rr[i] * SQLD + cc[i] * 8), Ksrc + (size_t)rr[i] * HD_ + cc[i] * 8);
        cp_async16(smem_u32(sV + rr[i] * VLD + cc[i] * 8),  Vsrc + (size_t)rr[i] * HD_ + cc[i] * 8);
    }
    cp_commit();
    cp_wait0();
    __syncthreads();
    // Q fragments: warp rows w*16..+16, 3 k16 steps
    uint32_t aQ[3][4];
    #pragma unroll
    for (int ks = 0; ks < 3; ks++) {
        uint32_t addr = smem_u32(sQ + (w * 16 + (lane & 15)) * SQLD + ks * 16 + (lane >> 4) * 8);
        ldsm_x4(aQ[ks][0], aQ[ks][1], aQ[ks][2], aQ[ks][3], addr);
    }
    float rsum[2] = {0.f, 0.f};
    float acc_o[6][4];
    #pragma unroll
    for (int nfv = 0; nfv < 6; nfv++)
        #pragma unroll
        for (int q = 0; q < 4; q++) acc_o[nfv][q] = 0.f;
    __half* srow = g_s + (size_t)bh * LQ * LK;
    const float cs = 0.14433757f * 1.44269504f;
    int lr0 = w * 16 + (lane >> 2);
    int buf = 0;
    for (int t = 0; t < 16; t++) {
        bool more = (t + 1) < 16;
        if (more) {
            const __half* Kn = Ksrc + (size_t)(t + 1) * 128 * HD_;
            const __half* Vn = Vsrc + (size_t)(t + 1) * 128 * HD_;
            int nb = buf ^ 1;
            #pragma unroll
            for (int i = 0; i < 3; i++) {
                cp_async16(smem_u32(sK + nb * 128 * SQLD + rr[i] * SQLD + cc[i] * 8),
                           Kn + (size_t)rr[i] * HD_ + cc[i] * 8);
                cp_async16(smem_u32(sV + nb * 128 * VLD + rr[i] * VLD + cc[i] * 8),
                           Vn + (size_t)rr[i] * HD_ + cc[i] * 8);
            }
            cp_commit();
        }
        // 8 chunks of 16 columns: QK -> exp epilogue -> PV, all in one pass
        #pragma unroll
        for (int ch16 = 0; ch16 < 8; ch16++) {
            // QK for this warp's 16 rows x 16 cols
            float facc[2][4];
            #pragma unroll
            for (int q = 0; q < 4; q++) { facc[0][q] = 0.f; facc[1][q] = 0.f; }
            #pragma unroll
            for (int ks = 0; ks < 3; ks++) {
                uint32_t k0r, k1r, k2r, k3r;
                uint32_t addr = smem_u32(sK + buf * 128 * SQLD +
                                         (ch16 * 16 + (lane & 15)) * SQLD + ks * 16 + (lane >> 4) * 8);
                ldsm_x4(k0r, k1r, k2r, k3r, addr);
                mma16816(facc[0], aQ[ks], k0r, k2r);
                mma16816(facc[1], aQ[ks], k1r, k3r);
            }
            // epilogue: exp, mask, rowsum, store fp16 (.cs)
            int c = t * 128 + ch16 * 16 + 2 * (lane & 3);
            float mk0 = sMsk[c],     mk1 = sMsk[c + 1];
            float mk2 = sMsk[c + 8], mk3 = sMsk[c + 9];
            float p00 = fast_exp2(facc[0][0] * cs) * mk0;
            float p01 = fast_exp2(facc[0][1] * cs) * mk1;
            float p10 = fast_exp2(facc[0][2] * cs) * mk0;
            float p11 = fast_exp2(facc[0][3] * cs) * mk1;
            float q00 = fast_exp2(facc[1][0] * cs) * mk2;
            float q01 = fast_exp2(facc[1][1] * cs) * mk3;
            float q10 = fast_exp2(facc[1][2] * cs) * mk2;
            float q11 = fast_exp2(facc[1][3] * cs) * mk3;
            rsum[0] += (p00 + p01) + (q00 + q01);
            rsum[1] += (p10 + p11) + (q10 + q11);
            __half2 h0 = __floats2half2_rn(p00, p01);
            __half2 h1 = __floats2half2_rn(p10, p11);
            __half2 h2 = __floats2half2_rn(q00, q01);
            __half2 h3 = __floats2half2_rn(q10, q11);
            uint32_t pA[4] = {*(uint32_t*)&h0, *(uint32_t*)&h1, *(uint32_t*)&h2, *(uint32_t*)&h3};
            stcs32(srow + (size_t)(m0 + lr0) * LK + c,         pA[0]);
            stcs32(srow + (size_t)(m0 + lr0 + 8) * LK + c,     pA[1]);
            stcs32(srow + (size_t)(m0 + lr0) * LK + c + 8,     pA[2]);
            stcs32(srow + (size_t)(m0 + lr0 + 8) * LK + c + 8, pA[3]);
            // PV: ctx += P_chunk(16x16) @ V_chunk(16x48)
            #pragma unroll
            for (int nfvp = 0; nfvp < 3; nfvp++) {
                uint32_t v0, v1, v2, v3;
                uint32_t addr = smem_u32(sV + buf * 128 * VLD +
                                         (ch16 * 16 + (lane & 15)) * VLD + nfvp * 16 + (lane >> 4) * 8);
                ldsm_x4_t(v0, v1, v2, v3, addr);
                mma16816(acc_o[2 * nfvp],     pA, v0, v1);
                mma16816(acc_o[2 * nfvp + 1], pA, v2, v3);
            }
        }
        if (more) {
            cp_wait0();
            __syncthreads();
            buf ^= 1;
        }
    }
    // row sums: reduce over quad lanes (cols)
    #pragma unroll
    for (int r = 0; r < 2; r++) {
        rsum[r] += __shfl_xor_sync(0xffffffffu, rsum[r], 1);
        rsum[r] += __shfl_xor_sync(0xffffffffu, rsum[r], 2);
    }
    float linv0 = 1.0f / rsum[0];
    float linv1 = 1.0f / rsum[1];
    if ((lane & 3) == 0) {
        g_linv[bh * LQ + m0 + lr0]     = linv0;
        g_linv[bh * LQ + m0 + lr0 + 8] = linv1;
    }
    // write ctx (fp16, per-token layout)
    int h = bh & 15;
    #pragma unroll
    for (int nfv = 0; nfv < 6; nfv++) {
        int d = nfv * 8 + 2 * (lane & 3);
        __half* dst0 = g_ctxh + ((size_t)b * LQ + m0 + lr0) * E_ + h * HD_ + d;
        __half* dst1 = g_ctxh + ((size_t)b * LQ + m0 + lr0 + 8) * E_ + h * HD_ + d;
        *(__half2*)dst0 = __floats2half2_rn(acc_o[nfv][0] * linv0, acc_o[nfv][1] * linv0);
        *(__half2*)dst1 = __floats2half2_rn(acc_o[nfv][2] * linv1, acc_o[nfv][3] * linv1);
    }
}

// ---------------- 6) attn_weights = mean over heads (normalized), fp16 streaming reads ----------------
__global__ void __launch_bounds__(256) k_meanheads(float* __restrict__ out) {
    size_t idx8 = (size_t)blockIdx.x * 256 + threadIdx.x;
    const size_t per_b8 = (size_t)LQ * LK / 8;
    int b = (int)(idx8 / per_b8);
    size_t rem8 = idx8 % per_b8;
    int q = (int)(rem8 >> 8);
    const uint4* base = (const uint4*)g_s + (size_t)b * H_ * per_b8 + rem8;
    float acc[8];
    #pragma unroll
    for (int j = 0; j < 8; j++) acc[j] = 0.f;
    #pragma unroll
    for (int h = 0; h < H_; h++) {
        float inv = g_linv[(b * H_ + h) * LQ + q];
        uint4 v = __ldcs(base + (size_t)h * per_b8);
        __half2* hh = (__half2*)&v;
        #pragma unroll
        for (int j = 0; j < 4; j++) {
            float2 f = __half22float2(hh[j]);
            acc[2 * j + 0] = fmaf(f.x, inv, acc[2 * j + 0]);
            acc[2 * j + 1] = fmaf(f.y, inv, acc[2 * j + 1]);
        }
    }
    const float ih = 1.0f / H_;
    float* dst = out + OUT_ATTN + idx8 * 8;
    *(float4*)(dst)     = make_float4(acc[0] * ih, acc[1] * ih, acc[2] * ih, acc[3] * ih);
    *(float4*)(dst + 4) = make_float4(acc[4] * ih, acc[5] * ih, acc[6] * ih, acc[7] * ih);
}

// ---------------- 8) attn_output = ctx @ out_w^T + out_b via HMMA ----------------
__global__ void __launch_bounds__(256) k_outproj_hmma(const float* __restrict__ out_b) {
    __shared__ __half sA[2][128 * QKLD];
    __shared__ __half sB[2][128 * QKLD];
    int m0 = blockIdx.y * 128, n0 = blockIdx.x * 128;
    int tid = threadIdx.x, lane = tid & 31, warp = tid >> 5;
    int wm = warp >> 1, wn = warp & 1;
    const __half* Asrc = g_ctxh + (size_t)m0 * E_;
    const __half* Bw = g_owh + (size_t)n0 * E_;
    int ur[2], uc8[2];
    #pragma unroll
    for (int i = 0; i < 2; i++) { int u4 = tid + i * 256; ur[i] = u4 >> 2; uc8[i] = u4 & 3; }
    #pragma unroll
    for (int i = 0; i < 2; i++) {
        *(uint4*)(sA[0] + ur[i] * QKLD + uc8[i] * 8) = *(const uint4*)(Asrc + (size_t)ur[i] * E_ + uc8[i] * 8);
        *(uint4*)(sB[0] + ur[i] * QKLD + uc8[i] * 8) = *(const uint4*)(Bw + (size_t)ur[i] * E_ + uc8[i] * 8);
    }
    __syncthreads();
    float acc[2][8][4];
    #pragma unroll
    for (int mf = 0; mf < 2; mf++)
        #pragma unroll
        for (int nf = 0; nf < 8; nf++)
            #pragma unroll
            for (int q = 0; q < 4; q++) acc[mf][nf][q] = 0.f;
    int buf = 0;
    uint4 apf[2], bpf[2];
    for (int kc = 0; kc < 24; kc++) {
        bool more = (kc + 1) < 24;
        if (more) {
            int kb = (kc + 1) * 32;
            #pragma unroll
            for (int i = 0; i < 2; i++) {
                apf[i] = *(const uint4*)(Asrc + (size_t)ur[i] * E_ + kb + uc8[i] * 8);
                bpf[i] = *(const uint4*)(Bw + (size_t)ur[i] * E_ + kb + uc8[i] * 8);
            }
        }
        #pragma unroll
        for (int ks = 0; ks < 2; ks++) {
            uint32_t a[2][4];
            #pragma unroll
            for (int mf = 0; mf < 2; mf++) {
                uint32_t addr = smem_u32(sA[buf] + (wm * 32 + mf * 16 + (lane & 15)) * QKLD + ks * 16 + (lane >> 4) * 8);
                ldsm_x4(a[mf][0], a[mf][1], a[mf][2], a[mf][3], addr);
            }
            #pragma unroll
            for (int nf = 0; nf < 8; nf++) {
                uint32_t b0, b1;
                uint32_t addr = smem_u32(sB[buf] + (wn * 64 + nf * 8 + (lane & 7)) * QKLD + ks * 16 + ((lane >> 3) & 1) * 8);
                ldsm_x2(b0, b1, addr);
                mma16816(acc[0][nf], a[0], b0, b1);
                mma16816(acc[1][nf], a[1], b0, b1);
            }
        }
        if (more) {
            int nb = buf ^ 1;
            #pragma unroll
            for (int i = 0; i < 2; i++) {
                *(uint4*)(sA[nb] + ur[i] * QKLD + uc8[i] * 8) = apf[i];
                *(uint4*)(sB[nb] + ur[i] * QKLD + uc8[i] * 8) = bpf[i];
            }
            __syncthreads();
            buf = nb;
        }
    }
    #pragma unroll
    for (int mf = 0; mf < 2; mf++) {
        int r0 = m0 + wm * 32 + mf * 16 + (lane >> 2);
        #pragma unroll
        for (int nf = 0; nf < 8; nf++) {
            int c0 = n0 + wn * 64 + nf * 8 + 2 * (lane & 3);
            float bv0 = out_b[c0], bv1 = out_b[c0 + 1];
            *(float2*)(g_ao + (size_t)r0 * E_ + c0)       = make_float2(acc[mf][nf][0] + bv0, acc[mf][nf][1] + bv1);
            *(float2*)(g_ao + (size_t)(r0 + 8) * E_ + c0) = make_float2(acc[mf][nf][2] + bv0, acc[mf][nf][3] + bv1);
        }
    }
}

// ---------------- 9) gate + residual + layernorm ----------------
__global__ void __launch_bounds__(256) k_final(const float* __restrict__ query,
                                               const float* __restrict__ ln_g,
                                               const float* __restrict__ ln_b,
                                               float* __restrict__ out) {
    __shared__ float xs[768];
    __shared__ float red[8];
    int t = blockIdx.x;
    int b = t >> 10;
    float sf = g_gate[b * 3 + 1], gv = g_gate[b * 3 + 2];
    const float* qrow = query + (size_t)t * E_;
    const float* arow = g_ao + (size_t)t * E_;
    int tid = threadIdx.x;
    float lsum = 0.f;
    for (int c = tid; c < E_; c += 256) {
        float q = qrow[c], a = arow[c];
        float gated = q * (1.f - gv) + a * sf * gv;
        float x = q + gated;
        xs[c] = x;
        lsum += x;
    }
    float mu = block_reduce_sum(lsum, red) * (1.0f / E_);
    float lv = 0.f;
    for (int c = tid; c < E_; c += 256) {
        float d = xs[c] - mu;
        lv += d * d;
    }
    float var = block_reduce_sum(lv, red) * (1.0f / E_);
    float inv = rsqrtf(var + 1e-5f);
    for (int c = tid; c < E_; c += 256)
        out[(size_t)t * E_ + c] = (xs[c] - mu) * inv * ln_g[c] + ln_b[c];
}

// ---------------- launcher (multi-stream fork/join, capture-safe) ----------------
extern "C" void kernel_launch(void* const* d_in, const int* in_sizes, int n_in,
                              void* d_out, int out_size) {
    const float* query = (const float*)d_in[0];
    const float* key   = (const float*)d_in[1];
    const float* value = (const float*)d_in[2];
    const unsigned char* mask = (const unsigned char*)d_in[3];
    const float* Wp1 = (const float*)d_in[4];
    const float* bp1 = (const float*)d_in[5];
    const float* Wp2 = (const float*)d_in[6];
    const float* bp2 = (const float*)d_in[7];
    const float* Wp3 = (const float*)d_in[8];
    const float* bp3 = (const float*)d_in[9];
    const float* in_proj_w = (const float*)d_in[10];
    const float* in_proj_b = (const float*)d_in[11];
    const float* out_w = (const float*)d_in[12];
    const float* out_b = (const float*)d_in[13];
    const float* ln_g  = (const float*)d_in[14];
    const float* ln_b  = (const float*)d_in[15];
    float* out = (float*)d_out;

    static bool once = []() {
        cudaFuncSetAttribute(k_scores_pv, cudaFuncAttributeMaxDynamicSharedMemorySize, SMEM_FUSED);
        return true;
    }();
    (void)once;

    static cudaStream_t s1 = []() {
        cudaStream_t s; cudaStreamCreateWithFlags(&s, cudaStreamNonBlocking); return s;
    }();
    static cudaEvent_t evFork = []() {
        cudaEvent_t e; cudaEventCreateWithFlags(&e, cudaEventDisableTiming); return e;
    }();
    static cudaEvent_t evMlp = []() {
        cudaEvent_t e; cudaEventCreateWithFlags(&e, cudaEventDisableTiming); return e;
    }();
    static cudaEvent_t evScores = []() {
        cudaEvent_t e; cudaEventCreateWithFlags(&e, cudaEventDisableTiming); return e;
    }();
    static cudaEvent_t evMean = []() {
        cudaEvent_t e; cudaEventCreateWithFlags(&e, cudaEventDisableTiming); return e;
    }();

    cudaEventRecord(evFork, 0);
    cudaStreamWaitEvent(s1, evFork, 0);
    k_colmean<<<dim3(8, B_, 2), 256, 0, s1>>>(query, key);
    k_mlp<<<B_, 256, 0, s1>>>(Wp1, bp1, Wp2, bp2, Wp3, bp3, out);
    cudaEventRecord(evMlp, s1);

    k_cvt_w<<<2304, 256>>>(in_proj_w, out_w);
    k_qkv_hmma<<<dim3(6, 160), 256>>>(query, key, value, in_proj_b);
    k_scores_pv<<<dim3(8, BH_), 256, SMEM_FUSED>>>(mask);
    cudaEventRecord(evScores, 0);

    cudaStreamWaitEvent(s1, evScores, 0);
    k_meanheads<<<(B_ * LQ * LK / 8) / 256, 256, 0, s1>>>(out);
    cudaEventRecord(evMean, s1);

    k_outproj_hmma<<<dim3(6, 32), 256>>>(out_b);
    cudaStreamWaitEvent(0, evMlp, 0);
    k_final<<<B_ * LQ, 256>>>(query, ln_g, ln_b, out);
    cudaStreamWaitEvent(0, evMean, 0);
}

// round 17
// speedup vs baseline: 2.8220x; 1.0000x over previous
#include <cuda_runtime.h>
#include <cuda_fp16.h>
#include <math.h>
#include <stdint.h>

#define B_   4
#define LQ   1024
#define LK   2048
#define E_   768
#define H_   16
#define HD_  48
#define BH_  (B_*H_)

// ---------------- scratch (device globals) ----------------
__device__ __half g_qh[BH_*LQ*HD_];                // fp16 q  [b][h][lq][d]
__device__ __half g_kh[BH_*LK*HD_];                // fp16 k
__device__ __half g_vh[BH_*LK*HD_];                // fp16 v
__device__ __half g_wh[3*E_*E_];                   // fp16 in_proj_w
__device__ __half g_owh[E_*E_];                    // fp16 out_w
__device__ __half g_s[(size_t)BH_*LQ*LK];          // exp(scores) fp16, unnormalized (268MB)
__device__ float  g_linv[BH_*LQ];                  // 1/rowsum (fp32)
__device__ __half g_ctxh[B_*LQ*E_];                // context fp16
__device__ float  g_ao[B_*LQ*E_];                  // attn_output fp32
__device__ float  g_pin_part[B_*8*1536];
__device__ float  g_gate[B_*3];

// output layout: output | attn_weights | num_heads | scale_factor | gate_value
#define OUT_ATTN ((size_t)B_*LQ*E_)
#define OUT_NH   (OUT_ATTN + (size_t)B_*LQ*LK)
#define OUT_SF   (OUT_NH + 4)
#define OUT_GV   (OUT_SF + 4)

// ---------------- helpers ----------------
__device__ __forceinline__ float fast_exp2(float x) {
    x = fmaxf(x, -120.0f);
    float k = rintf(x);
    float f = x - k;
    float p = 1.33336498e-3f;
    p = fmaf(p, f, 9.61011940e-3f);
    p = fmaf(p, f, 5.55041086e-2f);
    p = fmaf(p, f, 2.40226507e-1f);
    p = fmaf(p, f, 6.93147182e-1f);
    p = fmaf(p, f, 1.0f);
    int ik = (int)k;
    return p * __int_as_float((ik + 127) << 23);
}

__device__ __forceinline__ uint32_t smem_u32(const void* p) {
    uint32_t a;
    asm("{ .reg .u64 t; cvta.to.shared.u64 t, %1; cvt.u32.u64 %0, t; }" : "=r"(a) : "l"(p));
    return a;
}

__device__ __forceinline__ void ldsm_x4(uint32_t& r0, uint32_t& r1, uint32_t& r2, uint32_t& r3, uint32_t addr) {
    asm volatile("ldmatrix.sync.aligned.m8n8.x4.shared.b16 {%0,%1,%2,%3}, [%4];"
                 : "=r"(r0), "=r"(r1), "=r"(r2), "=r"(r3) : "r"(addr));
}
__device__ __forceinline__ void ldsm_x4_t(uint32_t& r0, uint32_t& r1, uint32_t& r2, uint32_t& r3, uint32_t addr) {
    asm volatile("ldmatrix.sync.aligned.m8n8.x4.trans.shared.b16 {%0,%1,%2,%3}, [%4];"
                 : "=r"(r0), "=r"(r1), "=r"(r2), "=r"(r3) : "r"(addr));
}
__device__ __forceinline__ void ldsm_x2(uint32_t& r0, uint32_t& r1, uint32_t addr) {
    asm volatile("ldmatrix.sync.aligned.m8n8.x2.shared.b16 {%0,%1}, [%2];"
                 : "=r"(r0), "=r"(r1) : "r"(addr));
}
__device__ __forceinline__ void mma16816(float c[4], const uint32_t a[4], uint32_t b0, uint32_t b1) {
    asm volatile("mma.sync.aligned.m16n8k16.row.col.f32.f16.f16.f32 "
                 "{%0,%1,%2,%3}, {%4,%5,%6,%7}, {%8,%9}, {%0,%1,%2,%3};"
                 : "+f"(c[0]), "+f"(c[1]), "+f"(c[2]), "+f"(c[3])
                 : "r"(a[0]), "r"(a[1]), "r"(a[2]), "r"(a[3]), "r"(b0), "r"(b1));
}
__device__ __forceinline__ void cp_async16(uint32_t dst, const void* src) {
    asm volatile("cp.async.cg.shared.global [%0], [%1], 16;" :: "r"(dst), "l"(src));
}
__device__ __forceinline__ void cp_commit() { asm volatile("cp.async.commit_group;"); }
__device__ __forceinline__ void cp_wait0()  { asm volatile("cp.async.wait_group 0;" ::: "memory"); }
__device__ __forceinline__ void stcs32(void* p, uint32_t v) {
    asm volatile("st.global.cs.b32 [%0], %1;" :: "l"(p), "r"(v));
}

__device__ __forceinline__ float block_reduce_sum(float v, float* red) {
    int tid = threadIdx.x;
    #pragma unroll
    for (int o = 16; o > 0; o >>= 1) v += __shfl_xor_sync(0xffffffffu, v, o);
    if ((tid & 31) == 0) red[tid >> 5] = v;
    __syncthreads();
    if (tid == 0) {
        float s = red[0];
        for (int i = 1; i < (int)(blockDim.x >> 5); i++) s += red[i];
        red[0] = s;
    }
    __syncthreads();
    float r = red[0];
    __syncthreads();
    return r;
}

// ---------------- 0) convert weights to fp16 ----------------
__global__ void k_cvt_w(const float* __restrict__ ipw, const float* __restrict__ ow) {
    int idx = blockIdx.x * 256 + threadIdx.x;
    const int n1 = 3 * E_ * E_ / 4;
    const int n2 = E_ * E_ / 4;
    if (idx < n1) {
        float4 v = ((const float4*)ipw)[idx];
        __half2 h0 = __floats2half2_rn(v.x, v.y);
        __half2 h1 = __floats2half2_rn(v.z, v.w);
        ((uint2*)g_wh)[idx] = make_uint2(*(uint32_t*)&h0, *(uint32_t*)&h1);
    } else if (idx < n1 + n2) {
        int j = idx - n1;
        float4 v = ((const float4*)ow)[j];
        __half2 h0 = __floats2half2_rn(v.x, v.y);
        __half2 h1 = __floats2half2_rn(v.z, v.w);
        ((uint2*)g_owh)[j] = make_uint2(*(uint32_t*)&h0, *(uint32_t*)&h1);
    }
}

// ---------------- 1) column means (partials) ----------------
__global__ void k_colmean(const float* __restrict__ q, const float* __restrict__ k) {
    int ch = blockIdx.x, b = blockIdx.y, which = blockIdx.z;
    const float* src = which ? k : q;
    int L = which ? LK : LQ;
    int rows = L / 8;
    const float* base = src + ((size_t)b * L + (size_t)ch * rows) * E_;
    for (int c = threadIdx.x; c < E_; c += 256) {
        float s = 0.f;
        for (int r = 0; r < rows; r++) s += base[(size_t)r * E_ + c];
        g_pin_part[(b * 8 + ch) * 1536 + which * E_ + c] = s;
    }
}

// ---------------- 2) gate MLP ----------------
__global__ void k_mlp(const float* __restrict__ Wp1, const float* __restrict__ bp1,
                      const float* __restrict__ Wp2, const float* __restrict__ bp2,
                      const float* __restrict__ Wp3, const float* __restrict__ bp3,
                      float* __restrict__ out) {
    __shared__ float pin[1536];
    __shared__ float h1[768];
    __shared__ float h2[384];
    int b = blockIdx.x, tid = threadIdx.x;
    for (int c = tid; c < 1536; c += 256) {
        float s = 0.f;
        for (int ch = 0; ch < 8; ch++) s += g_pin_part[(b * 8 + ch) * 1536 + c];
        pin[c] = s * ((c < 768) ? (1.0f / LQ) : (1.0f / LK));
    }
    __syncthreads();
    for (int o = tid; o < 768; o += 256) {
        const float* w = Wp1 + (size_t)o * 1536;
        float s = bp1[o];
        for (int i = 0; i < 1536; i++) s = fmaf(pin[i], w[i], s);
        h1[o] = fmaxf(s, 0.f);
    }
    __syncthreads();
    for (int o = tid; o < 384; o += 256) {
        const float* w = Wp2 + (size_t)o * 768;
        float s = bp2[o];
        for (int i = 0; i < 768; i++) s = fmaf(h1[i], w[i], s);
        h2[o] = fmaxf(s, 0.f);
    }
    __syncthreads();
    if (tid < 3) {
        const float* w = Wp3 + tid * 384;
        float s = bp3[tid];
        for (int i = 0; i < 384; i++) s = fmaf(h2[i], w[i], s);
        float sig = 1.f / (1.f + __expf(-s));
        if (tid == 0) {
            float nh = rintf(sig * 15.f + 1.f);
            g_gate[b * 3 + 0] = nh;
            out[OUT_NH + b] = nh;
        } else if (tid == 1) {
            float sf = sig * 0.5f + 0.5f;
            g_gate[b * 3 + 1] = sf;
            out[OUT_SF + b] = sf;
        } else {
            g_gate[b * 3 + 2] = sig;
            out[OUT_GV + b] = sig;
        }
    }
}

// ---------------- 3) QKV projection via HMMA ----------------
#define QKLD 40
__global__ void __launch_bounds__(256) k_qkv_hmma(
    const float* __restrict__ query, const float* __restrict__ key,
    const float* __restrict__ value, const float* __restrict__ bias) {
    __shared__ __half sA[2][128 * QKLD];
    __shared__ __half sB[2][128 * QKLD];
    int yt = blockIdx.y;
    int z, tokbase, Lseq;
    const float* src;
    __half* dst;
    if (yt < 32)      { z = 0; src = query; tokbase = yt * 128;        Lseq = LQ; dst = g_qh; }
    else if (yt < 96) { z = 1; src = key;   tokbase = (yt - 32) * 128; Lseq = LK; dst = g_kh; }
    else              { z = 2; src = value; tokbase = (yt - 96) * 128; Lseq = LK; dst = g_vh; }
    int n0 = blockIdx.x * 128;
    const __half* Bw = g_wh + ((size_t)(z * E_ + n0)) * E_;
    int tid = threadIdx.x, lane = tid & 31, warp = tid >> 5;
    int wm = warp >> 1, wn = warp & 1;
    int ar[4], ac4[4];
    #pragma unroll
    for (int i = 0; i < 4; i++) { int f4 = tid + i * 256; ar[i] = f4 >> 3; ac4[i] = f4 & 7; }
    int br[2], bc8[2];
    #pragma unroll
    for (int i = 0; i < 2; i++) { int u4 = tid + i * 256; br[i] = u4 >> 2; bc8[i] = u4 & 3; }
    #pragma unroll
    for (int i = 0; i < 4; i++) {
        float4 v = *(const float4*)(src + (size_t)(tokbase + ar[i]) * E_ + ac4[i] * 4);
        __half2 h0 = __floats2half2_rn(v.x, v.y);
        __half2 h1 = __floats2half2_rn(v.z, v.w);
        *(uint2*)(sA[0] + ar[i] * QKLD + ac4[i] * 4) = make_uint2(*(uint32_t*)&h0, *(uint32_t*)&h1);
    }
    #pragma unroll
    for (int i = 0; i < 2; i++)
        *(uint4*)(sB[0] + br[i] * QKLD + bc8[i] * 8) = *(const uint4*)(Bw + (size_t)br[i] * E_ + bc8[i] * 8);
    __syncthreads();
    float acc[2][8][4];
    #pragma unroll
    for (int mf = 0; mf < 2; mf++)
        #pragma unroll
        for (int nf = 0; nf < 8; nf++)
            #pragma unroll
            for (int q = 0; q < 4; q++) acc[mf][nf][q] = 0.f;
    int buf = 0;
    float4 apf[4];
    uint4 bpf[2];
    for (int kc = 0; kc < 24; kc++) {
        bool more = (kc + 1) < 24;
        if (more) {
            int kb = (kc + 1) * 32;
            #pragma unroll
            for (int i = 0; i < 4; i++)
                apf[i] = *(const float4*)(src + (size_t)(tokbase + ar[i]) * E_ + kb + ac4[i] * 4);
            #pragma unroll
            for (int i = 0; i < 2; i++)
                bpf[i] = *(const uint4*)(Bw + (size_t)br[i] * E_ + kb + bc8[i] * 8);
        }
        #pragma unroll
        for (int ks = 0; ks < 2; ks++) {
            uint32_t a[2][4];
            #pragma unroll
            for (int mf = 0; mf < 2; mf++) {
                uint32_t addr = smem_u32(sA[buf] + (wm * 32 + mf * 16 + (lane & 15)) * QKLD + ks * 16 + (lane >> 4) * 8);
                ldsm_x4(a[mf][0], a[mf][1], a[mf][2], a[mf][3], addr);
            }
            #pragma unroll
            for (int nf = 0; nf < 8; nf++) {
                uint32_t b0, b1;
                uint32_t addr = smem_u32(sB[buf] + (wn * 64 + nf * 8 + (lane & 7)) * QKLD + ks * 16 + ((lane >> 3) & 1) * 8);
                ldsm_x2(b0, b1, addr);
                mma16816(acc[0][nf], a[0], b0, b1);
                mma16816(acc[1][nf], a[1], b0, b1);
            }
        }
        if (more) {
            int nb = buf ^ 1;
            #pragma unroll
            for (int i = 0; i < 4; i++) {
                __half2 h0 = __floats2half2_rn(apf[i].x, apf[i].y);
                __half2 h1 = __floats2half2_rn(apf[i].z, apf[i].w);
                *(uint2*)(sA[nb] + ar[i] * QKLD + ac4[i] * 4) = make_uint2(*(uint32_t*)&h0, *(uint32_t*)&h1);
            }
            #pragma unroll
            for (int i = 0; i < 2; i++)
                *(uint4*)(sB[nb] + br[i] * QKLD + bc8[i] * 8) = bpf[i];
            __syncthreads();
            buf = nb;
        }
    }
    int bb = tokbase / Lseq;
    int sbase = tokbase % Lseq;
    #pragma unroll
    for (int mf = 0; mf < 2; mf++) {
        int r0 = wm * 32 + mf * 16 + (lane >> 2);
        #pragma unroll
        for (int nf = 0; nf < 8; nf++) {
            int c0 = n0 + wn * 64 + nf * 8 + 2 * (lane & 3);
            int h = c0 / HD_, d = c0 % HD_;
            float bv0 = bias[z * E_ + c0], bv1 = bias[z * E_ + c0 + 1];
            size_t a0 = (((size_t)(bb * H_ + h)) * Lseq + sbase + r0) * HD_ + d;
            size_t a1 = (((size_t)(bb * H_ + h)) * Lseq + sbase + r0 + 8) * HD_ + d;
            *(__half2*)(dst + a0) = __floats2half2_rn(acc[mf][nf][0] + bv0, acc[mf][nf][1] + bv1);
            *(__half2*)(dst + a1) = __floats2half2_rn(acc[mf][nf][2] + bv0, acc[mf][nf][3] + bv1);
        }
    }
}

// ------- 4) FUSED scores+PV: interleaved per-16-col chunk, register-dieted
//         (persistent pointers, 32-bit smem offsets), cp.async, 2 CTAs/SM. -------
#define SQLD 56
#define VLD  56
static constexpr int SMEM_FUSED =
    (128 * SQLD + 2 * 128 * SQLD + 2 * 128 * VLD) * 2 + LK * 4;   // 79872 B
#define KBUFB (128 * SQLD * 2)
#define VBUFB (128 * VLD * 2)
#define KTILEB (128 * HD_ * 2)
__global__ void __launch_bounds__(256, 2) k_scores_pv(const unsigned char* __restrict__ mask) {
    extern __shared__ __align__(16) char smem_raw[];
    __half* sQ = (__half*)smem_raw;                        // 128*SQLD
    __half* sK = sQ + 128 * SQLD;                          // 2 x 128*SQLD
    __half* sV = sK + 2 * 128 * SQLD;                      // 2 x 128*VLD
    float*  sMsk = (float*)(sV + 2 * 128 * VLD);           // LK
    int bh = blockIdx.y, m0 = blockIdx.x * 128, b = bh >> 4;
    int tid = threadIdx.x, lane = tid & 31, w = tid >> 5;
    {
        const __half* Qsrc = g_qh + ((size_t)bh * LQ + m0) * HD_;
        #pragma unroll
        for (int i = 0; i < 3; i++) {
            int idx = tid + i * 256;
            int r = idx / 6, c8 = idx % 6;
            *(uint4*)(sQ + r * SQLD + c8 * 8) = *(const uint4*)(Qsrc + (size_t)r * HD_ + c8 * 8);
        }
        #pragma unroll
        for (int i = 0; i < 8; i++) {
            int c = tid + i * 256;
            sMsk[c] = mask[b * LK + c] ? 0.f : 1.f;
        }
    }
    // persistent cp.async pointers/offsets
    const char* kq[3];
    const char* vq[3];
    uint32_t ksm[3], vsm[3];
    #pragma unroll
    for (int i = 0; i < 3; i++) {
        int idx = tid + i * 256;
        int r = idx / 6, c8 = idx % 6;
        kq[i] = (const char*)(g_kh + (size_t)bh * LK * HD_ + (size_t)r * HD_ + c8 * 8);
        vq[i] = (const char*)(g_vh + (size_t)bh * LK * HD_ + (size_t)r * HD_ + c8 * 8);
        ksm[i] = smem_u32(sK + r * SQLD + c8 * 8);
        vsm[i] = smem_u32(sV + r * VLD + c8 * 8);
    }
    #pragma unroll
    for (int i = 0; i < 3; i++) {
        cp_async16(ksm[i], kq[i]);
        cp_async16(vsm[i], vq[i]);
        kq[i] += KTILEB;
        vq[i] += KTILEB;
    }
    cp_commit();
    cp_wait0();
    __syncthreads();
    // Q fragments
    uint32_t aQ[3][4];
    {
        uint32_t qa = smem_u32(sQ) + (((w * 16 + (lane & 15)) * SQLD + (lane >> 4) * 8) << 1);
        #pragma unroll
        for (int ks = 0; ks < 3; ks++)
            ldsm_x4(aQ[ks][0], aQ[ks][1], aQ[ks][2], aQ[ks][3], qa + ks * 32);
    }
    float rsum[2] = {0.f, 0.f};
    float acc_o[6][4];
    #pragma unroll
    for (int nfv = 0; nfv < 6; nfv++)
        #pragma unroll
        for (int q = 0; q < 4; q++) acc_o[nfv][q] = 0.f;
    int lr0 = w * 16 + (lane >> 2);
    __half* srow0 = g_s + (size_t)bh * LQ * LK + (size_t)(m0 + lr0) * LK;
    __half* srow1 = srow0 + 8 * LK;
    const float cs = 0.14433757f * 1.44269504f;
    // lane bases for ldsm (32-bit)
    const uint32_t kla = smem_u32(sK) + (((lane & 15) * SQLD + (lane >> 4) * 8) << 1);
    const uint32_t vla = smem_u32(sV) + (((lane & 15) * VLD + (lane >> 4) * 8) << 1);
    int buf = 0;
    for (int t = 0; t < 16; t++) {
        bool more = (t + 1) < 16;
        if (more) {
            uint32_t bo = (buf ^ 1) ? 1u : 0u;
            #pragma unroll
            for (int i = 0; i < 3; i++) {
                cp_async16(ksm[i] + bo * KBUFB, kq[i]);
                cp_async16(vsm[i] + bo * VBUFB, vq[i]);
                kq[i] += KTILEB;
                vq[i] += KTILEB;
            }
            cp_commit();
        }
        uint32_t kb = kla + buf * KBUFB;
        uint32_t vb = vla + buf * VBUFB;
        int cbase = t * 128 + 2 * (lane & 3);
        #pragma unroll
        for (int ch16 = 0; ch16 < 8; ch16++) {
            float facc[2][4];
            #pragma unroll
            for (int q = 0; q < 4; q++) { facc[0][q] = 0.f; facc[1][q] = 0.f; }
            #pragma unroll
            for (int ks = 0; ks < 3; ks++) {
                uint32_t k0r, k1r, k2r, k3r;
                ldsm_x4(k0r, k1r, k2r, k3r, kb + ch16 * (16 * SQLD * 2) + ks * 32);
                mma16816(facc[0], aQ[ks], k0r, k2r);
                mma16816(facc[1], aQ[ks], k1r, k3r);
            }
            int c = cbase + ch16 * 16;
            float mk0 = sMsk[c],     mk1 = sMsk[c + 1];
            float mk2 = sMsk[c + 8], mk3 = sMsk[c + 9];
            float p00 = fast_exp2(facc[0][0] * cs) * mk0;
            float p01 = fast_exp2(facc[0][1] * cs) * mk1;
            float p10 = fast_exp2(facc[0][2] * cs) * mk0;
            float p11 = fast_exp2(facc[0][3] * cs) * mk1;
            float q00 = fast_exp2(facc[1][0] * cs) * mk2;
            float q01 = fast_exp2(facc[1][1] * cs) * mk3;
            float q10 = fast_exp2(facc[1][2] * cs) * mk2;
            float q11 = fast_exp2(facc[1][3] * cs) * mk3;
            rsum[0] += (p00 + p01) + (q00 + q01);
            rsum[1] += (p10 + p11) + (q10 + q11);
            __half2 h0 = __floats2half2_rn(p00, p01);
            __half2 h1 = __floats2half2_rn(p10, p11);
            __half2 h2 = __floats2half2_rn(q00, q01);
            __half2 h3 = __floats2half2_rn(q10, q11);
            uint32_t pA[4] = {*(uint32_t*)&h0, *(uint32_t*)&h1, *(uint32_t*)&h2, *(uint32_t*)&h3};
            stcs32(srow0 + c,     pA[0]);
            stcs32(srow1 + c,     pA[1]);
            stcs32(srow0 + c + 8, pA[2]);
            stcs32(srow1 + c + 8, pA[3]);
            #pragma unroll
            for (int nfvp = 0; nfvp < 3; nfvp++) {
                uint32_t v0, v1, v2, v3;
                ldsm_x4_t(v0, v1, v2, v3, vb + ch16 * (16 * VLD * 2) + nfvp * 32);
                mma16816(acc_o[2 * nfvp],     pA, v0, v1);
                mma16816(acc_o[2 * nfvp + 1], pA, v2, v3);
            }
        }
        if (more) {
            cp_wait0();
            __syncthreads();
            buf ^= 1;
        }
    }
    // row sums: reduce over quad lanes (cols)
    #pragma unroll
    for (int r = 0; r < 2; r++) {
        rsum[r] += __shfl_xor_sync(0xffffffffu, rsum[r], 1);
        rsum[r] += __shfl_xor_sync(0xffffffffu, rsum[r], 2);
    }
    float linv0 = 1.0f / rsum[0];
    float linv1 = 1.0f / rsum[1];
    if ((lane & 3) == 0) {
        g_linv[bh * LQ + m0 + lr0]     = linv0;
        g_linv[bh * LQ + m0 + lr0 + 8] = linv1;
    }
    // write ctx (fp16, per-token layout)
    int h = bh & 15;
    #pragma unroll
    for (int nfv = 0; nfv < 6; nfv++) {
        int d = nfv * 8 + 2 * (lane & 3);
        __half* dst0 = g_ctxh + ((size_t)b * LQ + m0 + lr0) * E_ + h * HD_ + d;
        __half* dst1 = g_ctxh + ((size_t)b * LQ + m0 + lr0 + 8) * E_ + h * HD_ + d;
        *(__half2*)dst0 = __floats2half2_rn(acc_o[nfv][0] * linv0, acc_o[nfv][1] * linv0);
        *(__half2*)dst1 = __floats2half2_rn(acc_o[nfv][2] * linv1, acc_o[nfv][3] * linv1);
    }
}

// ---------------- 6) attn_weights = mean over heads (normalized), fp16 streaming reads ----------------
__global__ void __launch_bounds__(256) k_meanheads(float* __restrict__ out) {
    size_t idx8 = (size_t)blockIdx.x * 256 + threadIdx.x;
    const size_t per_b8 = (size_t)LQ * LK / 8;
    int b = (int)(idx8 / per_b8);
    size_t rem8 = idx8 % per_b8;
    int q = (int)(rem8 >> 8);
    const uint4* base = (const uint4*)g_s + (size_t)b * H_ * per_b8 + rem8;
    float acc[8];
    #pragma unroll
    for (int j = 0; j < 8; j++) acc[j] = 0.f;
    #pragma unroll
    for (int h = 0; h < H_; h++) {
        float inv = g_linv[(b * H_ + h) * LQ + q];
        uint4 v = __ldcs(base + (size_t)h * per_b8);
        __half2* hh = (__half2*)&v;
        #pragma unroll
        for (int j = 0; j < 4; j++) {
            float2 f = __half22float2(hh[j]);
            acc[2 * j + 0] = fmaf(f.x, inv, acc[2 * j + 0]);
            acc[2 * j + 1] = fmaf(f.y, inv, acc[2 * j + 1]);
        }
    }
    const float ih = 1.0f / H_;
    float* dst = out + OUT_ATTN + idx8 * 8;
    *(float4*)(dst)     = make_float4(acc[0] * ih, acc[1] * ih, acc[2] * ih, acc[3] * ih);
    *(float4*)(dst + 4) = make_float4(acc[4] * ih, acc[5] * ih, acc[6] * ih, acc[7] * ih);
}

// ---------------- 8) attn_output = ctx @ out_w^T + out_b via HMMA ----------------
__global__ void __launch_bounds__(256) k_outproj_hmma(const float* __restrict__ out_b) {
    __shared__ __half sA[2][128 * QKLD];
    __shared__ __half sB[2][128 * QKLD];
    int m0 = blockIdx.y * 128, n0 = blockIdx.x * 128;
    int tid = threadIdx.x, lane = tid & 31, warp = tid >> 5;
    int wm = warp >> 1, wn = warp & 1;
    const __half* Asrc = g_ctxh + (size_t)m0 * E_;
    const __half* Bw = g_owh + (size_t)n0 * E_;
    int ur[2], uc8[2];
    #pragma unroll
    for (int i = 0; i < 2; i++) { int u4 = tid + i * 256; ur[i] = u4 >> 2; uc8[i] = u4 & 3; }
    #pragma unroll
    for (int i = 0; i < 2; i++) {
        *(uint4*)(sA[0] + ur[i] * QKLD + uc8[i] * 8) = *(const uint4*)(Asrc + (size_t)ur[i] * E_ + uc8[i] * 8);
        *(uint4*)(sB[0] + ur[i] * QKLD + uc8[i] * 8) = *(const uint4*)(Bw + (size_t)ur[i] * E_ + uc8[i] * 8);
    }
    __syncthreads();
    float acc[2][8][4];
    #pragma unroll
    for (int mf = 0; mf < 2; mf++)
        #pragma unroll
        for (int nf = 0; nf < 8; nf++)
            #pragma unroll
            for (int q = 0; q < 4; q++) acc[mf][nf][q] = 0.f;
    int buf = 0;
    uint4 apf[2], bpf[2];
    for (int kc = 0; kc < 24; kc++) {
        bool more = (kc + 1) < 24;
        if (more) {
            int kb = (kc + 1) * 32;
            #pragma unroll
            for (int i = 0; i < 2; i++) {
                apf[i] = *(const uint4*)(Asrc + (size_t)ur[i] * E_ + kb + uc8[i] * 8);
                bpf[i] = *(const uint4*)(Bw + (size_t)ur[i] * E_ + kb + uc8[i] * 8);
            }
        }
        #pragma unroll
        for (int ks = 0; ks < 2; ks++) {
            uint32_t a[2][4];
            #pragma unroll
            for (int mf = 0; mf < 2; mf++) {
                uint32_t addr = smem_u32(sA[buf] + (wm * 32 + mf * 16 + (lane & 15)) * QKLD + ks * 16 + (lane >> 4) * 8);
                ldsm_x4(a[mf][0], a[mf][1], a[mf][2], a[mf][3], addr);
            }
            #pragma unroll
            for (int nf = 0; nf < 8; nf++) {
                uint32_t b0, b1;
                uint32_t addr = smem_u32(sB[buf] + (wn * 64 + nf * 8 + (lane & 7)) * QKLD + ks * 16 + ((lane >> 3) & 1) * 8);
                ldsm_x2(b0, b1, addr);
                mma16816(acc[0][nf], a[0], b0, b1);
                mma16816(acc[1][nf], a[1], b0, b1);
            }
        }
        if (more) {
            int nb = buf ^ 1;
            #pragma unroll
            for (int i = 0; i < 2; i++) {
                *(uint4*)(sA[nb] + ur[i] * QKLD + uc8[i] * 8) = apf[i];
                *(uint4*)(sB[nb] + ur[i] * QKLD + uc8[i] * 8) = bpf[i];
            }
            __syncthreads();
            buf = nb;
        }
    }
    #pragma unroll
    for (int mf = 0; mf < 2; mf++) {
        int r0 = m0 + wm * 32 + mf * 16 + (lane >> 2);
        #pragma unroll
        for (int nf = 0; nf < 8; nf++) {
            int c0 = n0 + wn * 64 + nf * 8 + 2 * (lane & 3);
            float bv0 = out_b[c0], bv1 = out_b[c0 + 1];
            *(float2*)(g_ao + (size_t)r0 * E_ + c0)       = make_float2(acc[mf][nf][0] + bv0, acc[mf][nf][1] + bv1);
            *(float2*)(g_ao + (size_t)(r0 + 8) * E_ + c0) = make_float2(acc[mf][nf][2] + bv0, acc[mf][nf][3] + bv1);
        }
    }
}

// ---------------- 9) gate + residual + layernorm ----------------
__global__ void __launch_bounds__(256) k_final(const float* __restrict__ query,
                                               const float* __restrict__ ln_g,
                                               const float* __restrict__ ln_b,
                                               float* __restrict__ out) {
    __shared__ float xs[768];
    __shared__ float red[8];
    int t = blockIdx.x;
    int b = t >> 10;
    float sf = g_gate[b * 3 + 1], gv = g_gate[b * 3 + 2];
    const float* qrow = query + (size_t)t * E_;
    const float* arow = g_ao + (size_t)t * E_;
    int tid = threadIdx.x;
    float lsum = 0.f;
    for (int c = tid; c < E_; c += 256) {
        float q = qrow[c], a = arow[c];
        float gated = q * (1.f - gv) + a * sf * gv;
        float x = q + gated;
        xs[c] = x;
        lsum += x;
    }
    float mu = block_reduce_sum(lsum, red) * (1.0f / E_);
    float lv = 0.f;
    for (int c = tid; c < E_; c += 256) {
        float d = xs[c] - mu;
        lv += d * d;
    }
    float var = block_reduce_sum(lv, red) * (1.0f / E_);
    float inv = rsqrtf(var + 1e-5f);
    for (int c = tid; c < E_; c += 256)
        out[(size_t)t * E_ + c] = (xs[c] - mu) * inv * ln_g[c] + ln_b[c];
}

// ---------------- launcher (multi-stream fork/join, capture-safe) ----------------
extern "C" void kernel_launch(void* const* d_in, const int* in_sizes, int n_in,
                              void* d_out, int out_size) {
    const float* query = (const float*)d_in[0];
    const float* key   = (const float*)d_in[1];
    const float* value = (const float*)d_in[2];
    const unsigned char* mask = (const unsigned char*)d_in[3];
    const float* Wp1 = (const float*)d_in[4];
    const float* bp1 = (const float*)d_in[5];
    const float* Wp2 = (const float*)d_in[6];
    const float* bp2 = (const float*)d_in[7];
    const float* Wp3 = (const float*)d_in[8];
    const float* bp3 = (const float*)d_in[9];
    const float* in_proj_w = (const float*)d_in[10];
    const float* in_proj_b = (const float*)d_in[11];
    const float* out_w = (const float*)d_in[12];
    const float* out_b = (const float*)d_in[13];
    const float* ln_g  = (const float*)d_in[14];
    const float* ln_b  = (const float*)d_in[15];
    float* out = (float*)d_out;

    static bool once = []() {
        cudaFuncSetAttribute(k_scores_pv, cudaFuncAttributeMaxDynamicSharedMemorySize, SMEM_FUSED);
        return true;
    }();
    (void)once;

    static cudaStream_t s1 = []() {
        cudaStream_t s; cudaStreamCreateWithFlags(&s, cudaStreamNonBlocking); return s;
    }();
    static cudaEvent_t evFork = []() {
        cudaEvent_t e; cudaEventCreateWithFlags(&e, cudaEventDisableTiming); return e;
    }();
    static cudaEvent_t evMlp = []() {
        cudaEvent_t e; cudaEventCreateWithFlags(&e, cudaEventDisableTiming); return e;
    }();
    static cudaEvent_t evScores = []() {
        cudaEvent_t e; cudaEventCreateWithFlags(&e, cudaEventDisableTiming); return e;
    }();
    static cudaEvent_t evMean = []() {
        cudaEvent_t e; cudaEventCreateWithFlags(&e, cudaEventDisableTiming); return e;
    }();

    cudaEventRecord(evFork, 0);
    cudaStreamWaitEvent(s1, evFork, 0);
    k_colmean<<<dim3(8, B_, 2), 256, 0, s1>>>(query, key);
    k_mlp<<<B_, 256, 0, s1>>>(Wp1, bp1, Wp2, bp2, Wp3, bp3, out);
    cudaEventRecord(evMlp, s1);

    k_cvt_w<<<2304, 256>>>(in_proj_w, out_w);
    k_qkv_hmma<<<dim3(6, 160), 256>>>(query, key, value, in_proj_b);
    k_scores_pv<<<dim3(8, BH_), 256, SMEM_FUSED>>>(mask);
    cudaEventRecord(evScores, 0);

    cudaStreamWaitEvent(s1, evScores, 0);
    k_meanheads<<<(B_ * LQ * LK / 8) / 256, 256, 0, s1>>>(out);
    cudaEventRecord(evMean, s1);

    k_outproj_hmma<<<dim3(6, 32), 256>>>(out_b);
    cudaStreamWaitEvent(0, evMlp, 0);
    k_final<<<B_ * LQ, 256>>>(query, ln_g, ln_b, out);
    cudaStreamWaitEvent(0, evMean, 0);
}